// round 7
// baseline (speedup 1.0000x reference)
#include <cuda_runtime.h>
#include <cuda_bf16.h>
#include <cstdint>

// Problem constants
#define EMB   1024
#define HEADS 16
#define HD    64
#define BATCH 4
#define SEQ   2048
#define MTOT  (BATCH * SEQ)          // 8192 rows
#define E3    (3 * EMB)              // 3072

// ---------------------------------------------------------------------------
// Scratch (static device globals — allocation-free per harness rules)
// ---------------------------------------------------------------------------
__device__ float g_qkv[(size_t)MTOT * E3];   // [B*S, 3E]  q|k|v (fp32)
__device__ float g_ctx[(size_t)MTOT * EMB];  // [B*S, E]   attention output
__device__ __nv_bfloat16 g_a_hi[(size_t)MTOT * EMB];   // split of x / ctx
__device__ __nv_bfloat16 g_a_lo[(size_t)MTOT * EMB];
__device__ __nv_bfloat16 g_wq_hi[(size_t)E3 * EMB];    // W_qkv^T split [N,K]
__device__ __nv_bfloat16 g_wq_lo[(size_t)E3 * EMB];
__device__ __nv_bfloat16 g_wo_hi[(size_t)EMB * EMB];   // W_o^T split [N,K]
__device__ __nv_bfloat16 g_wo_lo[(size_t)EMB * EMB];
// attention operands (bf16)
__device__ __nv_bfloat16 g_q_hi[(size_t)MTOT * EMB];   // Q*0.125 hi
__device__ __nv_bfloat16 g_q_lo[(size_t)MTOT * EMB];   // Q*0.125 lo
__device__ __nv_bfloat16 g_k_hi[(size_t)MTOT * EMB];
__device__ __nv_bfloat16 g_k_lo[(size_t)MTOT * EMB];
__device__ __nv_bfloat16 g_v_hi[(size_t)MTOT * EMB];
__device__ __nv_bfloat16 g_v_lo[(size_t)MTOT * EMB];

// ---------------------------------------------------------------------------
// sm_80+ tensor-core primitives (legal on plain sm_100 target)
// ---------------------------------------------------------------------------
__device__ __forceinline__ uint32_t smem_u32(const void* p) {
    uint32_t a;
    asm("{ .reg .u64 t; cvta.to.shared.u64 t, %1; cvt.u32.u64 %0, t; }"
        : "=r"(a) : "l"(p));
    return a;
}

__device__ __forceinline__ void ldmx4(uint32_t* r, uint32_t addr) {
    asm volatile("ldmatrix.sync.aligned.m8n8.x4.shared.b16 {%0,%1,%2,%3}, [%4];"
                 : "=r"(r[0]), "=r"(r[1]), "=r"(r[2]), "=r"(r[3]) : "r"(addr));
}

__device__ __forceinline__ void ldmx4t(uint32_t* r, uint32_t addr) {
    asm volatile("ldmatrix.sync.aligned.m8n8.x4.trans.shared.b16 {%0,%1,%2,%3}, [%4];"
                 : "=r"(r[0]), "=r"(r[1]), "=r"(r[2]), "=r"(r[3]) : "r"(addr));
}

__device__ __forceinline__ void mma_bf16(float* d, const uint32_t* a,
                                         uint32_t b0, uint32_t b1) {
    asm volatile(
        "mma.sync.aligned.m16n8k16.row.col.f32.bf16.bf16.f32 "
        "{%0,%1,%2,%3}, {%4,%5,%6,%7}, {%8,%9}, {%0,%1,%2,%3};"
        : "+f"(d[0]), "+f"(d[1]), "+f"(d[2]), "+f"(d[3])
        : "r"(a[0]), "r"(a[1]), "r"(a[2]), "r"(a[3]), "r"(b0), "r"(b1));
}

__device__ __forceinline__ uint32_t pack_bf16x2(float lo, float hi) {
    __nv_bfloat162 p = __float22bfloat162_rn(make_float2(lo, hi));
    return *(uint32_t*)&p;
}

// ---------------------------------------------------------------------------
// Preprocessing: elementwise hi/lo bf16 split. mode 0: X=xext, mode 1: X=g_ctx
// ---------------------------------------------------------------------------
__global__ __launch_bounds__(256) void split_kernel(const float* __restrict__ Xext,
                                                    int mode, size_t n4)
{
    size_t i = (size_t)blockIdx.x * blockDim.x + threadIdx.x;
    if (i >= n4) return;
    const float* X = (mode == 0) ? Xext : (const float*)g_ctx;
    float4 v = ((const float4*)X)[i];
    __nv_bfloat16 h0 = __float2bfloat16(v.x);
    __nv_bfloat16 h1 = __float2bfloat16(v.y);
    __nv_bfloat16 h2 = __float2bfloat16(v.z);
    __nv_bfloat16 h3 = __float2bfloat16(v.w);
    __nv_bfloat162 H01; H01.x = h0; H01.y = h1;
    __nv_bfloat162 H23; H23.x = h2; H23.y = h3;
    __nv_bfloat162 L01;
    L01.x = __float2bfloat16(v.x - __bfloat162float(h0));
    L01.y = __float2bfloat16(v.y - __bfloat162float(h1));
    __nv_bfloat162 L23;
    L23.x = __float2bfloat16(v.z - __bfloat162float(h2));
    L23.y = __float2bfloat16(v.w - __bfloat162float(h3));
    *(__nv_bfloat162*)(g_a_hi + i * 4)     = H01;
    *(__nv_bfloat162*)(g_a_hi + i * 4 + 2) = H23;
    *(__nv_bfloat162*)(g_a_lo + i * 4)     = L01;
    *(__nv_bfloat162*)(g_a_lo + i * 4 + 2) = L23;
}

// ---------------------------------------------------------------------------
// Preprocessing: W [K,N] fp32 -> W^T hi/lo bf16 [N,K]. mode 0: g_wq, 1: g_wo
// ---------------------------------------------------------------------------
__global__ __launch_bounds__(256) void transpose_split_kernel(
    const float* __restrict__ W, int mode, int K, int N)
{
    __shared__ float t[32][33];
    const int n0 = blockIdx.x * 32, k0 = blockIdx.y * 32;
    const int tx = threadIdx.x, ty = threadIdx.y;
    for (int i = ty; i < 32; i += 8)
        t[i][tx] = W[(size_t)(k0 + i) * N + n0 + tx];
    __syncthreads();
    __nv_bfloat16* Th = mode ? g_wo_hi : g_wq_hi;
    __nv_bfloat16* Tl = mode ? g_wo_lo : g_wq_lo;
    for (int i = ty; i < 32; i += 8) {
        float v = t[tx][i];                    // = W[k0+tx][n0+i]
        __nv_bfloat16 h = __float2bfloat16(v);
        size_t o = (size_t)(n0 + i) * K + k0 + tx;
        Th[o] = h;
        Tl[o] = __float2bfloat16(v - __bfloat162float(h));
    }
}

// ---------------------------------------------------------------------------
// Convert g_qkv (fp32) -> bf16 attention operands (all hi/lo split; Q scaled).
// ---------------------------------------------------------------------------
__global__ __launch_bounds__(256) void qkv_convert_kernel()
{
    size_t i = (size_t)blockIdx.x * blockDim.x + threadIdx.x;
    if (i >= (size_t)MTOT * EMB / 4) return;
    size_t row = i >> 8;
    size_t c4  = (i & 255) * 4;
    const float* base = g_qkv + row * E3;
    size_t o = row * EMB + c4;

#pragma unroll
    for (int sec = 0; sec < 3; sec++) {
        float4 v = *(const float4*)(base + sec * EMB + c4);
        if (sec == 0) { v.x *= 0.125f; v.y *= 0.125f; v.z *= 0.125f; v.w *= 0.125f; }
        __nv_bfloat16 h0 = __float2bfloat16(v.x), h1 = __float2bfloat16(v.y);
        __nv_bfloat16 h2 = __float2bfloat16(v.z), h3 = __float2bfloat16(v.w);
        __nv_bfloat162 H01; H01.x = h0; H01.y = h1;
        __nv_bfloat162 H23; H23.x = h2; H23.y = h3;
        __nv_bfloat162 L01, L23;
        L01.x = __float2bfloat16(v.x - __bfloat162float(h0));
        L01.y = __float2bfloat16(v.y - __bfloat162float(h1));
        L23.x = __float2bfloat16(v.z - __bfloat162float(h2));
        L23.y = __float2bfloat16(v.w - __bfloat162float(h3));
        __nv_bfloat16* Hd = (sec == 0) ? g_q_hi : (sec == 1) ? g_k_hi : g_v_hi;
        __nv_bfloat16* Ld = (sec == 0) ? g_q_lo : (sec == 1) ? g_k_lo : g_v_lo;
        *(__nv_bfloat162*)(Hd + o)     = H01;
        *(__nv_bfloat162*)(Hd + o + 2) = H23;
        *(__nv_bfloat162*)(Ld + o)     = L01;
        *(__nv_bfloat162*)(Ld + o + 2) = L23;
    }
}

// ---------------------------------------------------------------------------
// Tensor-core bf16 3-term-split GEMM v2: C[M,N] = A[M,K]@B^T[N,K] + bias
// Block tile 256x128, 8 warps (4m x 2n), warp tile 64x64. BK=16, stride 24
// (48B rows: conflict-free ldmatrix + row-per-thread STS).
// 192 k-iters = 3 segments (Ah*Bh, Ah*Bl, Al*Bh) x 64.
// mode 0: C = g_qkv (N=3072); mode 1: C = Cext (N=1024)
// ---------------------------------------------------------------------------
#define STR2   24
#define A_ST   (256 * STR2)
#define B_ST   (128 * STR2)

__global__ __launch_bounds__(256) void tgemm_mma(
    const float* __restrict__ bias, float* __restrict__ Cext, int N, int mode)
{
    __shared__ alignas(16) __nv_bfloat16 As[2][A_ST];
    __shared__ alignas(16) __nv_bfloat16 Bs[2][B_ST];

    const int tid  = threadIdx.x;
    const int wid  = tid >> 5;
    const int lane = tid & 31;
    const int wm   = wid & 3;            // 0..3 : 64-row quarter
    const int wn   = wid >> 2;           // 0..1 : 64-col half
    const int m0   = blockIdx.y * 256;
    const int n0   = blockIdx.x * 128;
    const int K    = EMB;
    const int NIT  = 192;                // 3 * (K/16)

    const __nv_bfloat16* Bh = mode ? g_wo_hi : g_wq_hi;
    const __nv_bfloat16* Bl = mode ? g_wo_lo : g_wq_lo;
    float* C = mode ? Cext : (float*)g_qkv;

    float acc[4][8][4];
#pragma unroll
    for (int i = 0; i < 4; i++)
#pragma unroll
        for (int j = 0; j < 8; j++)
#pragma unroll
            for (int k = 0; k < 4; k++) acc[i][j][k] = 0.f;

    // Global/smem load coords: A row tid (2 float4), B row tid&127 col (tid>>7)*8.
    const int brow = tid & 127, bcol = (tid >> 7) * 8;

    // ldmatrix lane addressing
    const int a_lrow  = lane & 15;
    const int a_lcol  = (lane >> 4) * 8;
    const int b_lrow  = (lane & 7) + ((lane >> 4) << 3);
    const int b_lcol  = ((lane >> 3) & 1) * 8;

    const uint32_t sA = smem_u32(As);
    const uint32_t sB = smem_u32(Bs);

    // Prologue: tile 0 (segment 0: Ah, Bh) -> buffer 0
    *(float4*)&As[0][tid * STR2]     = *(const float4*)(g_a_hi + (size_t)(m0 + tid) * K);
    *(float4*)&As[0][tid * STR2 + 8] = *(const float4*)(g_a_hi + (size_t)(m0 + tid) * K + 8);
    *(float4*)&Bs[0][brow * STR2 + bcol] =
        *(const float4*)(Bh + (size_t)(n0 + brow) * K + bcol);
    __syncthreads();

    int buf = 0;
    for (int it = 0; it < NIT; it++) {
        // Prefetch next tile into registers
        float4 pa0, pa1, pb;
        if (it + 1 < NIT) {
            const int nit = it + 1;
            const int seg = nit >> 6;
            const int kk  = (nit & 63) * 16;
            const __nv_bfloat16* Ap = (seg < 2)  ? g_a_hi : g_a_lo;
            const __nv_bfloat16* Bp = (seg == 1) ? Bl : Bh;
            pa0 = *(const float4*)(Ap + (size_t)(m0 + tid) * K + kk);
            pa1 = *(const float4*)(Ap + (size_t)(m0 + tid) * K + kk + 8);
            pb  = *(const float4*)(Bp + (size_t)(n0 + brow) * K + kk + bcol);
        }

        const uint32_t baseA = sA + (uint32_t)buf * (A_ST * 2);
        const uint32_t baseB = sB + (uint32_t)buf * (B_ST * 2);
        uint32_t a[4][4], b[4][4];
#pragma unroll
        for (int mf = 0; mf < 4; mf++) {
            uint32_t addr = baseA +
                ((uint32_t)((wm * 64 + mf * 16 + a_lrow) * STR2 + a_lcol) << 1);
            ldmx4(a[mf], addr);
        }
#pragma unroll
        for (int nf2 = 0; nf2 < 4; nf2++) {
            uint32_t addr = baseB +
                ((uint32_t)((wn * 64 + nf2 * 16 + b_lrow) * STR2 + b_lcol) << 1);
            ldmx4(b[nf2], addr);
        }
#pragma unroll
        for (int mf = 0; mf < 4; mf++) {
#pragma unroll
            for (int nf = 0; nf < 8; nf++) {
                uint32_t b0 = b[nf >> 1][(nf & 1) * 2];
                uint32_t b1 = b[nf >> 1][(nf & 1) * 2 + 1];
                mma_bf16(acc[mf][nf], a[mf], b0, b1);
            }
        }

        if (it + 1 < NIT) {
            int nb = buf ^ 1;
            *(float4*)&As[nb][tid * STR2]        = pa0;
            *(float4*)&As[nb][tid * STR2 + 8]    = pa1;
            *(float4*)&Bs[nb][brow * STR2 + bcol] = pb;
        }
        __syncthreads();
        buf ^= 1;
    }

    // Epilogue
#pragma unroll
    for (int mf = 0; mf < 4; mf++) {
        const int r = m0 + wm * 64 + mf * 16 + (lane >> 2);
#pragma unroll
        for (int nf = 0; nf < 8; nf++) {
            const int c = n0 + wn * 64 + nf * 8 + (lane & 3) * 2;
            const float b0 = bias[c], b1 = bias[c + 1];
            float2 lo = make_float2(acc[mf][nf][0] + b0, acc[mf][nf][1] + b1);
            float2 hi = make_float2(acc[mf][nf][2] + b0, acc[mf][nf][3] + b1);
            *(float2*)&C[(size_t)r * N + c]       = lo;
            *(float2*)&C[(size_t)(r + 8) * N + c] = hi;
        }
    }
}

// ---------------------------------------------------------------------------
// Tensor-core flash attention (3-term QK split AND 3-term PV split).
// Block: (b,h) x 128-query tile; 8 warps x 16 query rows. Key-tiles of 64.
// ---------------------------------------------------------------------------
#define HPAD 72

__global__ __launch_bounds__(256) void attn_mma_kernel()
{
    __shared__ alignas(16) __nv_bfloat16 sKh[64 * HPAD];
    __shared__ alignas(16) __nv_bfloat16 sKl[64 * HPAD];
    __shared__ alignas(16) __nv_bfloat16 sVh[64 * HPAD];
    __shared__ alignas(16) __nv_bfloat16 sVl[64 * HPAD];

    const int tid  = threadIdx.x;
    const int w    = tid >> 5;
    const int lane = tid & 31;
    const int bh   = blockIdx.x;
    const int b    = bh >> 4;
    const int h    = bh & 15;
    const int q0   = blockIdx.y * 128;
    const int qoff = h * HD;
    const size_t grow0 = (size_t)(b * SEQ);

    const uint32_t aKh = smem_u32(sKh);
    const uint32_t aKl = smem_u32(sKl);
    const uint32_t aVh = smem_u32(sVh);
    const uint32_t aVl = smem_u32(sVl);

    const int a_lrow = lane & 15;
    const int a_lcol = (lane >> 4) * 8;
    const int b_lrow = (lane & 7) + ((lane >> 4) << 3);
    const int b_lcol = ((lane >> 3) & 1) * 8;
    const int v_lrow = lane & 15;
    const int v_lcol = (lane >> 4) * 8;

    // --- Load Q fragments (hi then lo) via smem staging ---
    uint32_t qh[4][4], ql[4][4];
    {
#pragma unroll
        for (int pass = 0; pass < 2; pass++) {
            const __nv_bfloat16* src = pass ? g_q_lo : g_q_hi;
            for (int u = 0; u < 4; u++) {
                int idx = tid + 256 * u;
                int r = idx >> 3, c8 = (idx & 7) * 8;
                *(float4*)&sKh[r * HPAD + c8] =
                    *(const float4*)(src + (grow0 + q0 + r) * EMB + qoff + c8);
            }
            __syncthreads();
            uint32_t (*dst)[4] = pass ? ql : qh;
#pragma unroll
            for (int d = 0; d < 4; d++) {
                uint32_t addr = aKh +
                    ((uint32_t)((w * 16 + a_lrow) * HPAD + d * 16 + a_lcol) << 1);
                ldmx4(dst[d], addr);
            }
            __syncthreads();
        }
    }

    float o[8][4];
#pragma unroll
    for (int i = 0; i < 8; i++)
#pragma unroll
        for (int j = 0; j < 4; j++) o[i][j] = 0.f;
    float m_lo = -1e30f, m_hi = -1e30f, l_lo = 0.f, l_hi = 0.f;

    for (int kt = 0; kt < SEQ / 64; kt++) {
        {
            const size_t rbase = (grow0 + kt * 64) * EMB + qoff;
#pragma unroll
            for (int u = 0; u < 2; u++) {
                int idx = tid * 2 + u;
                int r = idx >> 3, c8 = (idx & 7) * 8;
                size_t g = rbase + (size_t)r * EMB + c8;
                *(float4*)&sKh[r * HPAD + c8] = *(const float4*)(g_k_hi + g);
                *(float4*)&sKl[r * HPAD + c8] = *(const float4*)(g_k_lo + g);
                *(float4*)&sVh[r * HPAD + c8] = *(const float4*)(g_v_hi + g);
                *(float4*)&sVl[r * HPAD + c8] = *(const float4*)(g_v_lo + g);
            }
        }
        __syncthreads();

        // S = Qh*Kh + Ql*Kh + Qh*Kl
        float s[8][4];
#pragma unroll
        for (int i = 0; i < 8; i++)
#pragma unroll
            for (int j = 0; j < 4; j++) s[i][j] = 0.f;

#pragma unroll
        for (int d = 0; d < 4; d++) {
#pragma unroll
            for (int nf2 = 0; nf2 < 4; nf2++) {
                uint32_t off = ((uint32_t)((nf2 * 16 + b_lrow) * HPAD
                                           + d * 16 + b_lcol) << 1);
                uint32_t bk[4], bl[4];
                ldmx4(bk, aKh + off);
                ldmx4(bl, aKl + off);
#pragma unroll
                for (int half = 0; half < 2; half++) {
                    float* acc = s[nf2 * 2 + half];
                    uint32_t k0 = bk[half * 2], k1 = bk[half * 2 + 1];
                    mma_bf16(acc, qh[d], k0, k1);
                    mma_bf16(acc, ql[d], k0, k1);
                    mma_bf16(acc, qh[d], bl[half * 2], bl[half * 2 + 1]);
                }
            }
        }

        // Online softmax
        float rmax_lo = -1e30f, rmax_hi = -1e30f;
#pragma unroll
        for (int j = 0; j < 8; j++) {
            rmax_lo = fmaxf(rmax_lo, fmaxf(s[j][0], s[j][1]));
            rmax_hi = fmaxf(rmax_hi, fmaxf(s[j][2], s[j][3]));
        }
        rmax_lo = fmaxf(rmax_lo, __shfl_xor_sync(0xffffffffu, rmax_lo, 1));
        rmax_lo = fmaxf(rmax_lo, __shfl_xor_sync(0xffffffffu, rmax_lo, 2));
        rmax_hi = fmaxf(rmax_hi, __shfl_xor_sync(0xffffffffu, rmax_hi, 1));
        rmax_hi = fmaxf(rmax_hi, __shfl_xor_sync(0xffffffffu, rmax_hi, 2));

        float mn_lo = fmaxf(m_lo, rmax_lo);
        float mn_hi = fmaxf(m_hi, rmax_hi);
        float alpha_lo = __expf(m_lo - mn_lo);
        float alpha_hi = __expf(m_hi - mn_hi);

        uint32_t pl[8], ph[8];     // P hi parts (packed bf16x2)
        uint32_t rl[8], rh[8];     // P lo residual parts
        float rs_lo = 0.f, rs_hi = 0.f;
#pragma unroll
        for (int j = 0; j < 8; j++) {
            float p0 = __expf(s[j][0] - mn_lo);
            float p1 = __expf(s[j][1] - mn_lo);
            float p2 = __expf(s[j][2] - mn_hi);
            float p3 = __expf(s[j][3] - mn_hi);
            rs_lo += p0 + p1;
            rs_hi += p2 + p3;
            __nv_bfloat16 b0 = __float2bfloat16(p0), b1 = __float2bfloat16(p1);
            __nv_bfloat16 b2 = __float2bfloat16(p2), b3 = __float2bfloat16(p3);
            __nv_bfloat162 P01; P01.x = b0; P01.y = b1;
            __nv_bfloat162 P23; P23.x = b2; P23.y = b3;
            pl[j] = *(uint32_t*)&P01;
            ph[j] = *(uint32_t*)&P23;
            rl[j] = pack_bf16x2(p0 - __bfloat162float(b0),
                                p1 - __bfloat162float(b1));
            rh[j] = pack_bf16x2(p2 - __bfloat162float(b2),
                                p3 - __bfloat162float(b3));
        }
        rs_lo += __shfl_xor_sync(0xffffffffu, rs_lo, 1);
        rs_lo += __shfl_xor_sync(0xffffffffu, rs_lo, 2);
        rs_hi += __shfl_xor_sync(0xffffffffu, rs_hi, 1);
        rs_hi += __shfl_xor_sync(0xffffffffu, rs_hi, 2);

        l_lo = l_lo * alpha_lo + rs_lo;
        l_hi = l_hi * alpha_hi + rs_hi;
        m_lo = mn_lo;
        m_hi = mn_hi;
#pragma unroll
        for (int nf = 0; nf < 8; nf++) {
            o[nf][0] *= alpha_lo; o[nf][1] *= alpha_lo;
            o[nf][2] *= alpha_hi; o[nf][3] *= alpha_hi;
        }

        // O += Ph@Vh + Pl@Vh + Ph@Vl
#pragma unroll
        for (int ks = 0; ks < 4; ks++) {
            uint32_t A1[4] = {pl[ks * 2], ph[ks * 2], pl[ks * 2 + 1], ph[ks * 2 + 1]};
            uint32_t A2[4] = {rl[ks * 2], rh[ks * 2], rl[ks * 2 + 1], rh[ks * 2 + 1]};
#pragma unroll
            for (int nc = 0; nc < 4; nc++) {
                uint32_t soff = ((uint32_t)((ks * 16 + v_lrow) * HPAD
                                            + nc * 16 + v_lcol) << 1);
                uint32_t bv[4], bw[4];
                ldmx4t(bv, aVh + soff);
                ldmx4t(bw, aVl + soff);
                mma_bf16(o[nc * 2],     A1, bv[0], bv[1]);
                mma_bf16(o[nc * 2 + 1], A1, bv[2], bv[3]);
                mma_bf16(o[nc * 2],     A2, bv[0], bv[1]);
                mma_bf16(o[nc * 2 + 1], A2, bv[2], bv[3]);
                mma_bf16(o[nc * 2],     A1, bw[0], bw[1]);
                mma_bf16(o[nc * 2 + 1], A1, bw[2], bw[3]);
            }
        }
        __syncthreads();
    }

    // Normalize and write ctx (fp32)
    const float inv_lo = 1.0f / l_lo;
    const float inv_hi = 1.0f / l_hi;
    const size_t row_lo = grow0 + q0 + w * 16 + (lane >> 2);
    const size_t row_hi = row_lo + 8;
#pragma unroll
    for (int nf = 0; nf < 8; nf++) {
        const int c = qoff + nf * 8 + (lane & 3) * 2;
        *(float2*)&g_ctx[row_lo * EMB + c] =
            make_float2(o[nf][0] * inv_lo, o[nf][1] * inv_lo);
        *(float2*)&g_ctx[row_hi * EMB + c] =
            make_float2(o[nf][2] * inv_hi, o[nf][3] * inv_hi);
    }
}

// ---------------------------------------------------------------------------
// Launch: pure kernel launches (graph-capture safe, no runtime API calls).
// ---------------------------------------------------------------------------
extern "C" void kernel_launch(void* const* d_in, const int* in_sizes, int n_in,
                              void* d_out, int out_size)
{
    const float* x     = (const float*)d_in[0];
    const float* W_qkv = (const float*)d_in[1];
    const float* b_qkv = (const float*)d_in[2];
    const float* W_o   = (const float*)d_in[3];
    const float* b_o   = (const float*)d_in[4];
    float* out = (float*)d_out;

    const size_t n4 = (size_t)MTOT * EMB / 4;

    // Preprocess: split x, transpose+split weights
    split_kernel<<<(unsigned)((n4 + 255) / 256), 256>>>(x, 0, n4);
    transpose_split_kernel<<<dim3(E3 / 32, EMB / 32), dim3(32, 8)>>>(W_qkv, 0, EMB, E3);
    transpose_split_kernel<<<dim3(EMB / 32, EMB / 32), dim3(32, 8)>>>(W_o, 1, EMB, EMB);

    // 1) QKV projection on tensor cores -> g_qkv
    tgemm_mma<<<dim3(E3 / 128, MTOT / 256), 256>>>(b_qkv, nullptr, E3, 0);

    // 2) Convert qkv -> bf16 attention operands, run tensor-core attention
    qkv_convert_kernel<<<(unsigned)((n4 + 255) / 256), 256>>>();
    attn_mma_kernel<<<dim3(BATCH * HEADS, SEQ / 128), 256>>>();

    // 3) Split ctx, output projection on tensor cores -> d_out
    split_kernel<<<(unsigned)((n4 + 255) / 256), 256>>>(nullptr, 1, n4);
    tgemm_mma<<<dim3(EMB / 128, MTOT / 256), 256>>>(b_o, out, EMB, 1);
}

// round 8
// speedup vs baseline: 1.3557x; 1.3557x over previous
#include <cuda_runtime.h>
#include <cuda_bf16.h>
#include <cstdint>

// Problem constants
#define EMB   1024
#define HEADS 16
#define HD    64
#define BATCH 4
#define SEQ   2048
#define MTOT  (BATCH * SEQ)          // 8192 rows
#define E3    (3 * EMB)              // 3072

// ---------------------------------------------------------------------------
// Scratch (static device globals — allocation-free per harness rules)
// ---------------------------------------------------------------------------
__device__ float g_qkv[(size_t)MTOT * E3];   // [B*S, 3E]  q|k|v (fp32)
__device__ float g_ctx[(size_t)MTOT * EMB];  // [B*S, E]   attention output
__device__ __nv_bfloat16 g_a_hi[(size_t)MTOT * EMB];   // split of x / ctx
__device__ __nv_bfloat16 g_a_lo[(size_t)MTOT * EMB];
__device__ __nv_bfloat16 g_wq_hi[(size_t)E3 * EMB];    // W_qkv^T split [N,K]
__device__ __nv_bfloat16 g_wq_lo[(size_t)E3 * EMB];
__device__ __nv_bfloat16 g_wo_hi[(size_t)EMB * EMB];   // W_o^T split [N,K]
__device__ __nv_bfloat16 g_wo_lo[(size_t)EMB * EMB];
// attention operands (bf16)
__device__ __nv_bfloat16 g_q_hi[(size_t)MTOT * EMB];   // Q*0.125 hi
__device__ __nv_bfloat16 g_q_lo[(size_t)MTOT * EMB];   // Q*0.125 lo
__device__ __nv_bfloat16 g_k_hi[(size_t)MTOT * EMB];
__device__ __nv_bfloat16 g_k_lo[(size_t)MTOT * EMB];
__device__ __nv_bfloat16 g_v_hi[(size_t)MTOT * EMB];
__device__ __nv_bfloat16 g_v_lo[(size_t)MTOT * EMB];

// ---------------------------------------------------------------------------
// sm_80+ primitives (legal on plain sm_100 target)
// ---------------------------------------------------------------------------
__device__ __forceinline__ uint32_t smem_u32(const void* p) {
    uint32_t a;
    asm("{ .reg .u64 t; cvta.to.shared.u64 t, %1; cvt.u32.u64 %0, t; }"
        : "=r"(a) : "l"(p));
    return a;
}

__device__ __forceinline__ void ldmx4(uint32_t* r, uint32_t addr) {
    asm volatile("ldmatrix.sync.aligned.m8n8.x4.shared.b16 {%0,%1,%2,%3}, [%4];"
                 : "=r"(r[0]), "=r"(r[1]), "=r"(r[2]), "=r"(r[3]) : "r"(addr));
}

__device__ __forceinline__ void ldmx4t(uint32_t* r, uint32_t addr) {
    asm volatile("ldmatrix.sync.aligned.m8n8.x4.trans.shared.b16 {%0,%1,%2,%3}, [%4];"
                 : "=r"(r[0]), "=r"(r[1]), "=r"(r[2]), "=r"(r[3]) : "r"(addr));
}

__device__ __forceinline__ void mma_bf16(float* d, const uint32_t* a,
                                         uint32_t b0, uint32_t b1) {
    asm volatile(
        "mma.sync.aligned.m16n8k16.row.col.f32.bf16.bf16.f32 "
        "{%0,%1,%2,%3}, {%4,%5,%6,%7}, {%8,%9}, {%0,%1,%2,%3};"
        : "+f"(d[0]), "+f"(d[1]), "+f"(d[2]), "+f"(d[3])
        : "r"(a[0]), "r"(a[1]), "r"(a[2]), "r"(a[3]), "r"(b0), "r"(b1));
}

__device__ __forceinline__ uint32_t pack_bf16x2(float lo, float hi) {
    __nv_bfloat162 p = __float22bfloat162_rn(make_float2(lo, hi));
    return *(uint32_t*)&p;
}

__device__ __forceinline__ void cp_async16(uint32_t smem_dst, const void* gptr) {
    asm volatile("cp.async.cg.shared.global [%0], [%1], 16;"
                 :: "r"(smem_dst), "l"(gptr));
}
__device__ __forceinline__ void cp_commit() {
    asm volatile("cp.async.commit_group;");
}
__device__ __forceinline__ void cp_wait1() {
    asm volatile("cp.async.wait_group 1;");
}

// ---------------------------------------------------------------------------
// Preprocessing: elementwise hi/lo bf16 split. mode 0: X=xext, mode 1: X=g_ctx
// ---------------------------------------------------------------------------
__global__ __launch_bounds__(256) void split_kernel(const float* __restrict__ Xext,
                                                    int mode, size_t n4)
{
    size_t i = (size_t)blockIdx.x * blockDim.x + threadIdx.x;
    if (i >= n4) return;
    const float* X = (mode == 0) ? Xext : (const float*)g_ctx;
    float4 v = ((const float4*)X)[i];
    __nv_bfloat16 h0 = __float2bfloat16(v.x);
    __nv_bfloat16 h1 = __float2bfloat16(v.y);
    __nv_bfloat16 h2 = __float2bfloat16(v.z);
    __nv_bfloat16 h3 = __float2bfloat16(v.w);
    __nv_bfloat162 H01; H01.x = h0; H01.y = h1;
    __nv_bfloat162 H23; H23.x = h2; H23.y = h3;
    __nv_bfloat162 L01;
    L01.x = __float2bfloat16(v.x - __bfloat162float(h0));
    L01.y = __float2bfloat16(v.y - __bfloat162float(h1));
    __nv_bfloat162 L23;
    L23.x = __float2bfloat16(v.z - __bfloat162float(h2));
    L23.y = __float2bfloat16(v.w - __bfloat162float(h3));
    *(__nv_bfloat162*)(g_a_hi + i * 4)     = H01;
    *(__nv_bfloat162*)(g_a_hi + i * 4 + 2) = H23;
    *(__nv_bfloat162*)(g_a_lo + i * 4)     = L01;
    *(__nv_bfloat162*)(g_a_lo + i * 4 + 2) = L23;
}

// ---------------------------------------------------------------------------
// Preprocessing: W [K,N] fp32 -> W^T hi/lo bf16 [N,K]. mode 0: g_wq, 1: g_wo
// ---------------------------------------------------------------------------
__global__ __launch_bounds__(256) void transpose_split_kernel(
    const float* __restrict__ W, int mode, int K, int N)
{
    __shared__ float t[32][33];
    const int n0 = blockIdx.x * 32, k0 = blockIdx.y * 32;
    const int tx = threadIdx.x, ty = threadIdx.y;
    for (int i = ty; i < 32; i += 8)
        t[i][tx] = W[(size_t)(k0 + i) * N + n0 + tx];
    __syncthreads();
    __nv_bfloat16* Th = mode ? g_wo_hi : g_wq_hi;
    __nv_bfloat16* Tl = mode ? g_wo_lo : g_wq_lo;
    for (int i = ty; i < 32; i += 8) {
        float v = t[tx][i];                    // = W[k0+tx][n0+i]
        __nv_bfloat16 h = __float2bfloat16(v);
        size_t o = (size_t)(n0 + i) * K + k0 + tx;
        Th[o] = h;
        Tl[o] = __float2bfloat16(v - __bfloat162float(h));
    }
}

// ---------------------------------------------------------------------------
// Convert g_qkv (fp32) -> bf16 attention operands (all hi/lo split; Q scaled).
// ---------------------------------------------------------------------------
__global__ __launch_bounds__(256) void qkv_convert_kernel()
{
    size_t i = (size_t)blockIdx.x * blockDim.x + threadIdx.x;
    if (i >= (size_t)MTOT * EMB / 4) return;
    size_t row = i >> 8;
    size_t c4  = (i & 255) * 4;
    const float* base = g_qkv + row * E3;
    size_t o = row * EMB + c4;

#pragma unroll
    for (int sec = 0; sec < 3; sec++) {
        float4 v = *(const float4*)(base + sec * EMB + c4);
        if (sec == 0) { v.x *= 0.125f; v.y *= 0.125f; v.z *= 0.125f; v.w *= 0.125f; }
        __nv_bfloat16 h0 = __float2bfloat16(v.x), h1 = __float2bfloat16(v.y);
        __nv_bfloat16 h2 = __float2bfloat16(v.z), h3 = __float2bfloat16(v.w);
        __nv_bfloat162 H01; H01.x = h0; H01.y = h1;
        __nv_bfloat162 H23; H23.x = h2; H23.y = h3;
        __nv_bfloat162 L01, L23;
        L01.x = __float2bfloat16(v.x - __bfloat162float(h0));
        L01.y = __float2bfloat16(v.y - __bfloat162float(h1));
        L23.x = __float2bfloat16(v.z - __bfloat162float(h2));
        L23.y = __float2bfloat16(v.w - __bfloat162float(h3));
        __nv_bfloat16* Hd = (sec == 0) ? g_q_hi : (sec == 1) ? g_k_hi : g_v_hi;
        __nv_bfloat16* Ld = (sec == 0) ? g_q_lo : (sec == 1) ? g_k_lo : g_v_lo;
        *(__nv_bfloat162*)(Hd + o)     = H01;
        *(__nv_bfloat162*)(Hd + o + 2) = H23;
        *(__nv_bfloat162*)(Ld + o)     = L01;
        *(__nv_bfloat162*)(Ld + o + 2) = L23;
    }
}

// ---------------------------------------------------------------------------
// Tensor-core bf16 3-term-split GEMM v3: C[M,N] = A[M,K]@B^T[N,K] + bias
// Block 128x128, 8 warps (2m x 4n), warp 64x32 (R5 layout, regs-friendly).
// BK=16, row stride 24 (48B, conflict-free), 3-stage cp.async pipeline.
// 192 k16-iters = 3 segments (Ah*Bh, Ah*Bl, Al*Bh) x 64.
// mode 0: C = g_qkv (N=3072); mode 1: C = Cext (N=1024)
// ---------------------------------------------------------------------------
#define STR3   24
#define STG_E  (128 * STR3)              // elements per stage per matrix

__global__ __launch_bounds__(256, 2) void tgemm_mma(
    const float* __restrict__ bias, float* __restrict__ Cext, int N, int mode)
{
    __shared__ alignas(16) __nv_bfloat16 As[3][STG_E];   // 3 x 6KB
    __shared__ alignas(16) __nv_bfloat16 Bs[3][STG_E];   // 3 x 6KB

    const int tid  = threadIdx.x;
    const int wid  = tid >> 5;
    const int lane = tid & 31;
    const int wm   = wid & 1;            // 64-row half
    const int wn   = wid >> 1;           // 32-col quarter
    const int m0   = blockIdx.y * 128;
    const int n0   = blockIdx.x * 128;
    const int K    = EMB;
    const int NIT  = 192;                // 3 * (K/16)

    const __nv_bfloat16* Bh = mode ? g_wo_hi : g_wq_hi;
    const __nv_bfloat16* Bl = mode ? g_wo_lo : g_wq_lo;
    float* C = mode ? Cext : (float*)g_qkv;

    float acc[4][4][4];
#pragma unroll
    for (int i = 0; i < 4; i++)
#pragma unroll
        for (int j = 0; j < 4; j++)
#pragma unroll
            for (int k = 0; k < 4; k++) acc[i][j][k] = 0.f;

    // Per-thread load coords: 256 float4 per 128x16 tile -> 1 per thread.
    const int lr = tid >> 1;             // row 0..127
    const int lc = (tid & 1) * 8;        // col 0 or 8

    // ldmatrix lane addressing
    const int a_lrow  = lane & 15;
    const int a_lcol  = (lane >> 4) * 8;
    const int b_lrow  = (lane & 7) + ((lane >> 4) << 3);
    const int b_lcol  = ((lane >> 3) & 1) * 8;

    const uint32_t sA = smem_u32(As);
    const uint32_t sB = smem_u32(Bs);
    const uint32_t dstA = sA + ((uint32_t)(lr * STR3 + lc) << 1);
    const uint32_t dstB = sB + ((uint32_t)(lr * STR3 + lc) << 1);

    // Issue tile `t` into stage t%3
    auto issue_tile = [&](int t) {
        const int seg = t >> 6;
        const int kk  = (t & 63) * 16;
        const __nv_bfloat16* Ap = (seg < 2)  ? g_a_hi : g_a_lo;
        const __nv_bfloat16* Bp = (seg == 1) ? Bl : Bh;
        const uint32_t so = (uint32_t)(t % 3) * (STG_E * 2);
        cp_async16(dstA + so, Ap + (size_t)(m0 + lr) * K + kk + lc);
        cp_async16(dstB + so, Bp + (size_t)(n0 + lr) * K + kk + lc);
    };

    // Prologue: stages 0,1 in flight
    issue_tile(0); cp_commit();
    issue_tile(1); cp_commit();

    for (int it = 0; it < NIT; it++) {
        cp_wait1();                       // tile `it` resident
        __syncthreads();

        const uint32_t so    = (uint32_t)(it % 3) * (STG_E * 2);
        const uint32_t baseA = sA + so;
        const uint32_t baseB = sB + so;

        uint32_t a[4][4], b[2][4];
#pragma unroll
        for (int mf = 0; mf < 4; mf++) {
            uint32_t addr = baseA +
                ((uint32_t)((wm * 64 + mf * 16 + a_lrow) * STR3 + a_lcol) << 1);
            ldmx4(a[mf], addr);
        }
#pragma unroll
        for (int nf2 = 0; nf2 < 2; nf2++) {
            uint32_t addr = baseB +
                ((uint32_t)((wn * 32 + nf2 * 16 + b_lrow) * STR3 + b_lcol) << 1);
            ldmx4(b[nf2], addr);
        }
#pragma unroll
        for (int mf = 0; mf < 4; mf++) {
#pragma unroll
            for (int nf = 0; nf < 4; nf++) {
                uint32_t b0 = b[nf >> 1][(nf & 1) * 2];
                uint32_t b1 = b[nf >> 1][(nf & 1) * 2 + 1];
                mma_bf16(acc[mf][nf], a[mf], b0, b1);
            }
        }

        // Overwriting stage (it+2)%3 is safe: all warps finished computing
        // tile it-1 (same stage) before the __syncthreads above.
        if (it + 2 < NIT) issue_tile(it + 2);
        cp_commit();                      // keep group counting uniform
    }

    // Epilogue
#pragma unroll
    for (int mf = 0; mf < 4; mf++) {
        const int r = m0 + wm * 64 + mf * 16 + (lane >> 2);
#pragma unroll
        for (int nf = 0; nf < 4; nf++) {
            const int c = n0 + wn * 32 + nf * 8 + (lane & 3) * 2;
            const float b0 = bias[c], b1 = bias[c + 1];
            float2 lo = make_float2(acc[mf][nf][0] + b0, acc[mf][nf][1] + b1);
            float2 hi = make_float2(acc[mf][nf][2] + b0, acc[mf][nf][3] + b1);
            *(float2*)&C[(size_t)r * N + c]       = lo;
            *(float2*)&C[(size_t)(r + 8) * N + c] = hi;
        }
    }
}

// ---------------------------------------------------------------------------
// Tensor-core flash attention (3-term QK split AND 3-term PV split).
// Unchanged from round 7 (rel_err 9.2e-6 proven).
// ---------------------------------------------------------------------------
#define HPAD 72

__global__ __launch_bounds__(256) void attn_mma_kernel()
{
    __shared__ alignas(16) __nv_bfloat16 sKh[64 * HPAD];
    __shared__ alignas(16) __nv_bfloat16 sKl[64 * HPAD];
    __shared__ alignas(16) __nv_bfloat16 sVh[64 * HPAD];
    __shared__ alignas(16) __nv_bfloat16 sVl[64 * HPAD];

    const int tid  = threadIdx.x;
    const int w    = tid >> 5;
    const int lane = tid & 31;
    const int bh   = blockIdx.x;
    const int b    = bh >> 4;
    const int h    = bh & 15;
    const int q0   = blockIdx.y * 128;
    const int qoff = h * HD;
    const size_t grow0 = (size_t)(b * SEQ);

    const uint32_t aKh = smem_u32(sKh);
    const uint32_t aKl = smem_u32(sKl);
    const uint32_t aVh = smem_u32(sVh);
    const uint32_t aVl = smem_u32(sVl);

    const int a_lrow = lane & 15;
    const int a_lcol = (lane >> 4) * 8;
    const int b_lrow = (lane & 7) + ((lane >> 4) << 3);
    const int b_lcol = ((lane >> 3) & 1) * 8;
    const int v_lrow = lane & 15;
    const int v_lcol = (lane >> 4) * 8;

    // --- Load Q fragments (hi then lo) via smem staging ---
    uint32_t qh[4][4], ql[4][4];
    {
#pragma unroll
        for (int pass = 0; pass < 2; pass++) {
            const __nv_bfloat16* src = pass ? g_q_lo : g_q_hi;
            for (int u = 0; u < 4; u++) {
                int idx = tid + 256 * u;
                int r = idx >> 3, c8 = (idx & 7) * 8;
                *(float4*)&sKh[r * HPAD + c8] =
                    *(const float4*)(src + (grow0 + q0 + r) * EMB + qoff + c8);
            }
            __syncthreads();
            uint32_t (*dst)[4] = pass ? ql : qh;
#pragma unroll
            for (int d = 0; d < 4; d++) {
                uint32_t addr = aKh +
                    ((uint32_t)((w * 16 + a_lrow) * HPAD + d * 16 + a_lcol) << 1);
                ldmx4(dst[d], addr);
            }
            __syncthreads();
        }
    }

    float o[8][4];
#pragma unroll
    for (int i = 0; i < 8; i++)
#pragma unroll
        for (int j = 0; j < 4; j++) o[i][j] = 0.f;
    float m_lo = -1e30f, m_hi = -1e30f, l_lo = 0.f, l_hi = 0.f;

    for (int kt = 0; kt < SEQ / 64; kt++) {
        {
            const size_t rbase = (grow0 + kt * 64) * EMB + qoff;
#pragma unroll
            for (int u = 0; u < 2; u++) {
                int idx = tid * 2 + u;
                int r = idx >> 3, c8 = (idx & 7) * 8;
                size_t g = rbase + (size_t)r * EMB + c8;
                *(float4*)&sKh[r * HPAD + c8] = *(const float4*)(g_k_hi + g);
                *(float4*)&sKl[r * HPAD + c8] = *(const float4*)(g_k_lo + g);
                *(float4*)&sVh[r * HPAD + c8] = *(const float4*)(g_v_hi + g);
                *(float4*)&sVl[r * HPAD + c8] = *(const float4*)(g_v_lo + g);
            }
        }
        __syncthreads();

        // S = Qh*Kh + Ql*Kh + Qh*Kl
        float s[8][4];
#pragma unroll
        for (int i = 0; i < 8; i++)
#pragma unroll
            for (int j = 0; j < 4; j++) s[i][j] = 0.f;

#pragma unroll
        for (int d = 0; d < 4; d++) {
#pragma unroll
            for (int nf2 = 0; nf2 < 4; nf2++) {
                uint32_t off = ((uint32_t)((nf2 * 16 + b_lrow) * HPAD
                                           + d * 16 + b_lcol) << 1);
                uint32_t bk[4], bl[4];
                ldmx4(bk, aKh + off);
                ldmx4(bl, aKl + off);
#pragma unroll
                for (int half = 0; half < 2; half++) {
                    float* acc = s[nf2 * 2 + half];
                    uint32_t k0 = bk[half * 2], k1 = bk[half * 2 + 1];
                    mma_bf16(acc, qh[d], k0, k1);
                    mma_bf16(acc, ql[d], k0, k1);
                    mma_bf16(acc, qh[d], bl[half * 2], bl[half * 2 + 1]);
                }
            }
        }

        // Online softmax
        float rmax_lo = -1e30f, rmax_hi = -1e30f;
#pragma unroll
        for (int j = 0; j < 8; j++) {
            rmax_lo = fmaxf(rmax_lo, fmaxf(s[j][0], s[j][1]));
            rmax_hi = fmaxf(rmax_hi, fmaxf(s[j][2], s[j][3]));
        }
        rmax_lo = fmaxf(rmax_lo, __shfl_xor_sync(0xffffffffu, rmax_lo, 1));
        rmax_lo = fmaxf(rmax_lo, __shfl_xor_sync(0xffffffffu, rmax_lo, 2));
        rmax_hi = fmaxf(rmax_hi, __shfl_xor_sync(0xffffffffu, rmax_hi, 1));
        rmax_hi = fmaxf(rmax_hi, __shfl_xor_sync(0xffffffffu, rmax_hi, 2));

        float mn_lo = fmaxf(m_lo, rmax_lo);
        float mn_hi = fmaxf(m_hi, rmax_hi);
        float alpha_lo = __expf(m_lo - mn_lo);
        float alpha_hi = __expf(m_hi - mn_hi);

        uint32_t pl[8], ph[8];
        uint32_t rl[8], rh[8];
        float rs_lo = 0.f, rs_hi = 0.f;
#pragma unroll
        for (int j = 0; j < 8; j++) {
            float p0 = __expf(s[j][0] - mn_lo);
            float p1 = __expf(s[j][1] - mn_lo);
            float p2 = __expf(s[j][2] - mn_hi);
            float p3 = __expf(s[j][3] - mn_hi);
            rs_lo += p0 + p1;
            rs_hi += p2 + p3;
            __nv_bfloat16 b0 = __float2bfloat16(p0), b1 = __float2bfloat16(p1);
            __nv_bfloat16 b2 = __float2bfloat16(p2), b3 = __float2bfloat16(p3);
            __nv_bfloat162 P01; P01.x = b0; P01.y = b1;
            __nv_bfloat162 P23; P23.x = b2; P23.y = b3;
            pl[j] = *(uint32_t*)&P01;
            ph[j] = *(uint32_t*)&P23;
            rl[j] = pack_bf16x2(p0 - __bfloat162float(b0),
                                p1 - __bfloat162float(b1));
            rh[j] = pack_bf16x2(p2 - __bfloat162float(b2),
                                p3 - __bfloat162float(b3));
        }
        rs_lo += __shfl_xor_sync(0xffffffffu, rs_lo, 1);
        rs_lo += __shfl_xor_sync(0xffffffffu, rs_lo, 2);
        rs_hi += __shfl_xor_sync(0xffffffffu, rs_hi, 1);
        rs_hi += __shfl_xor_sync(0xffffffffu, rs_hi, 2);

        l_lo = l_lo * alpha_lo + rs_lo;
        l_hi = l_hi * alpha_hi + rs_hi;
        m_lo = mn_lo;
        m_hi = mn_hi;
#pragma unroll
        for (int nf = 0; nf < 8; nf++) {
            o[nf][0] *= alpha_lo; o[nf][1] *= alpha_lo;
            o[nf][2] *= alpha_hi; o[nf][3] *= alpha_hi;
        }

        // O += Ph@Vh + Pl@Vh + Ph@Vl
#pragma unroll
        for (int ks = 0; ks < 4; ks++) {
            uint32_t A1[4] = {pl[ks * 2], ph[ks * 2], pl[ks * 2 + 1], ph[ks * 2 + 1]};
            uint32_t A2[4] = {rl[ks * 2], rh[ks * 2], rl[ks * 2 + 1], rh[ks * 2 + 1]};
#pragma unroll
            for (int nc = 0; nc < 4; nc++) {
                uint32_t soff = ((uint32_t)((ks * 16 + v_lrow) * HPAD
                                            + nc * 16 + v_lcol) << 1);
                uint32_t bv[4], bw[4];
                ldmx4t(bv, aVh + soff);
                ldmx4t(bw, aVl + soff);
                mma_bf16(o[nc * 2],     A1, bv[0], bv[1]);
                mma_bf16(o[nc * 2 + 1], A1, bv[2], bv[3]);
                mma_bf16(o[nc * 2],     A2, bv[0], bv[1]);
                mma_bf16(o[nc * 2 + 1], A2, bv[2], bv[3]);
                mma_bf16(o[nc * 2],     A1, bw[0], bw[1]);
                mma_bf16(o[nc * 2 + 1], A1, bw[2], bw[3]);
            }
        }
        __syncthreads();
    }

    // Normalize and write ctx (fp32)
    const float inv_lo = 1.0f / l_lo;
    const float inv_hi = 1.0f / l_hi;
    const size_t row_lo = grow0 + q0 + w * 16 + (lane >> 2);
    const size_t row_hi = row_lo + 8;
#pragma unroll
    for (int nf = 0; nf < 8; nf++) {
        const int c = qoff + nf * 8 + (lane & 3) * 2;
        *(float2*)&g_ctx[row_lo * EMB + c] =
            make_float2(o[nf][0] * inv_lo, o[nf][1] * inv_lo);
        *(float2*)&g_ctx[row_hi * EMB + c] =
            make_float2(o[nf][2] * inv_hi, o[nf][3] * inv_hi);
    }
}

// ---------------------------------------------------------------------------
// Launch: pure kernel launches (graph-capture safe, no runtime API calls).
// ---------------------------------------------------------------------------
extern "C" void kernel_launch(void* const* d_in, const int* in_sizes, int n_in,
                              void* d_out, int out_size)
{
    const float* x     = (const float*)d_in[0];
    const float* W_qkv = (const float*)d_in[1];
    const float* b_qkv = (const float*)d_in[2];
    const float* W_o   = (const float*)d_in[3];
    const float* b_o   = (const float*)d_in[4];
    float* out = (float*)d_out;

    const size_t n4 = (size_t)MTOT * EMB / 4;

    // Preprocess: split x, transpose+split weights
    split_kernel<<<(unsigned)((n4 + 255) / 256), 256>>>(x, 0, n4);
    transpose_split_kernel<<<dim3(E3 / 32, EMB / 32), dim3(32, 8)>>>(W_qkv, 0, EMB, E3);
    transpose_split_kernel<<<dim3(EMB / 32, EMB / 32), dim3(32, 8)>>>(W_o, 1, EMB, EMB);

    // 1) QKV projection on tensor cores -> g_qkv
    tgemm_mma<<<dim3(E3 / 128, MTOT / 128), 256>>>(b_qkv, nullptr, E3, 0);

    // 2) Convert qkv -> bf16 attention operands, run tensor-core attention
    qkv_convert_kernel<<<(unsigned)((n4 + 255) / 256), 256>>>();
    attn_mma_kernel<<<dim3(BATCH * HEADS, SEQ / 128), 256>>>();

    // 3) Split ctx, output projection on tensor cores -> d_out
    split_kernel<<<(unsigned)((n4 + 255) / 256), 256>>>(nullptr, 1, n4);
    tgemm_mma<<<dim3(EMB / 128, MTOT / 128), 256>>>(b_o, out, EMB, 1);
}

// round 9
// speedup vs baseline: 1.9769x; 1.4582x over previous
#include <cuda_runtime.h>
#include <cuda_bf16.h>
#include <cuda_fp16.h>
#include <cstdint>

// Problem constants
#define EMB   1024
#define HEADS 16
#define HD    64
#define BATCH 4
#define SEQ   2048
#define MTOT  (BATCH * SEQ)          // 8192 rows
#define E3    (3 * EMB)              // 3072

// ---------------------------------------------------------------------------
// Scratch (static device globals — allocation-free per harness rules)
// ---------------------------------------------------------------------------
__device__ float g_qkv[(size_t)MTOT * E3];   // [B*S, 3E]  q|k|v (fp32)
__device__ float g_ctx[(size_t)MTOT * EMB];  // [B*S, E]   attention output
__device__ __nv_bfloat16 g_a_hi[(size_t)MTOT * EMB];   // split of x / ctx
__device__ __nv_bfloat16 g_a_lo[(size_t)MTOT * EMB];
__device__ __nv_bfloat16 g_wq_hi[(size_t)E3 * EMB];    // W_qkv^T split [N,K]
__device__ __nv_bfloat16 g_wq_lo[(size_t)E3 * EMB];
__device__ __nv_bfloat16 g_wo_hi[(size_t)EMB * EMB];   // W_o^T split [N,K]
__device__ __nv_bfloat16 g_wo_lo[(size_t)EMB * EMB];
// attention operands (fp16)
__device__ __half g_qf[(size_t)MTOT * EMB];  // Q * 0.125
__device__ __half g_kf[(size_t)MTOT * EMB];
__device__ __half g_vf[(size_t)MTOT * EMB];

// ---------------------------------------------------------------------------
// sm_80+ primitives (legal on plain sm_100 target)
// ---------------------------------------------------------------------------
__device__ __forceinline__ uint32_t smem_u32(const void* p) {
    uint32_t a;
    asm("{ .reg .u64 t; cvta.to.shared.u64 t, %1; cvt.u32.u64 %0, t; }"
        : "=r"(a) : "l"(p));
    return a;
}

__device__ __forceinline__ void ldmx4(uint32_t* r, uint32_t addr) {
    asm volatile("ldmatrix.sync.aligned.m8n8.x4.shared.b16 {%0,%1,%2,%3}, [%4];"
                 : "=r"(r[0]), "=r"(r[1]), "=r"(r[2]), "=r"(r[3]) : "r"(addr));
}

__device__ __forceinline__ void ldmx4t(uint32_t* r, uint32_t addr) {
    asm volatile("ldmatrix.sync.aligned.m8n8.x4.trans.shared.b16 {%0,%1,%2,%3}, [%4];"
                 : "=r"(r[0]), "=r"(r[1]), "=r"(r[2]), "=r"(r[3]) : "r"(addr));
}

__device__ __forceinline__ void mma_bf16(float* d, const uint32_t* a,
                                         uint32_t b0, uint32_t b1) {
    asm volatile(
        "mma.sync.aligned.m16n8k16.row.col.f32.bf16.bf16.f32 "
        "{%0,%1,%2,%3}, {%4,%5,%6,%7}, {%8,%9}, {%0,%1,%2,%3};"
        : "+f"(d[0]), "+f"(d[1]), "+f"(d[2]), "+f"(d[3])
        : "r"(a[0]), "r"(a[1]), "r"(a[2]), "r"(a[3]), "r"(b0), "r"(b1));
}

__device__ __forceinline__ void mma_f16(float* d, const uint32_t* a,
                                        uint32_t b0, uint32_t b1) {
    asm volatile(
        "mma.sync.aligned.m16n8k16.row.col.f32.f16.f16.f32 "
        "{%0,%1,%2,%3}, {%4,%5,%6,%7}, {%8,%9}, {%0,%1,%2,%3};"
        : "+f"(d[0]), "+f"(d[1]), "+f"(d[2]), "+f"(d[3])
        : "r"(a[0]), "r"(a[1]), "r"(a[2]), "r"(a[3]), "r"(b0), "r"(b1));
}

__device__ __forceinline__ void cp_async16(uint32_t smem_dst, const void* gptr) {
    asm volatile("cp.async.cg.shared.global [%0], [%1], 16;"
                 :: "r"(smem_dst), "l"(gptr));
}
__device__ __forceinline__ void cp_commit() {
    asm volatile("cp.async.commit_group;");
}
__device__ __forceinline__ void cp_wait1() {
    asm volatile("cp.async.wait_group 1;");
}

// ---------------------------------------------------------------------------
// Preprocessing: elementwise hi/lo bf16 split. mode 0: X=xext, mode 1: X=g_ctx
// ---------------------------------------------------------------------------
__global__ __launch_bounds__(256) void split_kernel(const float* __restrict__ Xext,
                                                    int mode, size_t n4)
{
    size_t i = (size_t)blockIdx.x * blockDim.x + threadIdx.x;
    if (i >= n4) return;
    const float* X = (mode == 0) ? Xext : (const float*)g_ctx;
    float4 v = ((const float4*)X)[i];
    __nv_bfloat16 h0 = __float2bfloat16(v.x);
    __nv_bfloat16 h1 = __float2bfloat16(v.y);
    __nv_bfloat16 h2 = __float2bfloat16(v.z);
    __nv_bfloat16 h3 = __float2bfloat16(v.w);
    __nv_bfloat162 H01; H01.x = h0; H01.y = h1;
    __nv_bfloat162 H23; H23.x = h2; H23.y = h3;
    __nv_bfloat162 L01;
    L01.x = __float2bfloat16(v.x - __bfloat162float(h0));
    L01.y = __float2bfloat16(v.y - __bfloat162float(h1));
    __nv_bfloat162 L23;
    L23.x = __float2bfloat16(v.z - __bfloat162float(h2));
    L23.y = __float2bfloat16(v.w - __bfloat162float(h3));
    *(__nv_bfloat162*)(g_a_hi + i * 4)     = H01;
    *(__nv_bfloat162*)(g_a_hi + i * 4 + 2) = H23;
    *(__nv_bfloat162*)(g_a_lo + i * 4)     = L01;
    *(__nv_bfloat162*)(g_a_lo + i * 4 + 2) = L23;
}

// ---------------------------------------------------------------------------
// Preprocessing: W [K,N] fp32 -> W^T hi/lo bf16 [N,K]. mode 0: g_wq, 1: g_wo
// ---------------------------------------------------------------------------
__global__ __launch_bounds__(256) void transpose_split_kernel(
    const float* __restrict__ W, int mode, int K, int N)
{
    __shared__ float t[32][33];
    const int n0 = blockIdx.x * 32, k0 = blockIdx.y * 32;
    const int tx = threadIdx.x, ty = threadIdx.y;
    for (int i = ty; i < 32; i += 8)
        t[i][tx] = W[(size_t)(k0 + i) * N + n0 + tx];
    __syncthreads();
    __nv_bfloat16* Th = mode ? g_wo_hi : g_wq_hi;
    __nv_bfloat16* Tl = mode ? g_wo_lo : g_wq_lo;
    for (int i = ty; i < 32; i += 8) {
        float v = t[tx][i];                    // = W[k0+tx][n0+i]
        __nv_bfloat16 h = __float2bfloat16(v);
        size_t o = (size_t)(n0 + i) * K + k0 + tx;
        Th[o] = h;
        Tl[o] = __float2bfloat16(v - __bfloat162float(h));
    }
}

// ---------------------------------------------------------------------------
// Convert g_qkv (fp32) -> fp16 attention operands (Q scaled by 0.125).
// ---------------------------------------------------------------------------
__global__ __launch_bounds__(256) void qkv_convert_kernel()
{
    size_t i = (size_t)blockIdx.x * blockDim.x + threadIdx.x;
    if (i >= (size_t)MTOT * EMB / 4) return;
    size_t row = i >> 8;
    size_t c4  = (i & 255) * 4;
    const float* base = g_qkv + row * E3;
    size_t o = row * EMB + c4;

    float4 q = *(const float4*)(base + c4);
    float4 k = *(const float4*)(base + EMB + c4);
    float4 v = *(const float4*)(base + 2 * EMB + c4);
    __half2 q01 = __floats2half2_rn(q.x * 0.125f, q.y * 0.125f);
    __half2 q23 = __floats2half2_rn(q.z * 0.125f, q.w * 0.125f);
    __half2 k01 = __floats2half2_rn(k.x, k.y);
    __half2 k23 = __floats2half2_rn(k.z, k.w);
    __half2 v01 = __floats2half2_rn(v.x, v.y);
    __half2 v23 = __floats2half2_rn(v.z, v.w);
    *(__half2*)(g_qf + o)     = q01;
    *(__half2*)(g_qf + o + 2) = q23;
    *(__half2*)(g_kf + o)     = k01;
    *(__half2*)(g_kf + o + 2) = k23;
    *(__half2*)(g_vf + o)     = v01;
    *(__half2*)(g_vf + o + 2) = v23;
}

// ---------------------------------------------------------------------------
// Tensor-core bf16 3-term-split GEMM v3 (unchanged from round 8, 619us):
// Block 128x128, 8 warps (2m x 4n), warp 64x32, BK=16, stride 24,
// 3-stage cp.async pipeline. mode 0: C=g_qkv (N=3072); mode 1: C=Cext.
// ---------------------------------------------------------------------------
#define STR3   24
#define STG_E  (128 * STR3)

__global__ __launch_bounds__(256, 2) void tgemm_mma(
    const float* __restrict__ bias, float* __restrict__ Cext, int N, int mode)
{
    __shared__ alignas(16) __nv_bfloat16 As[3][STG_E];
    __shared__ alignas(16) __nv_bfloat16 Bs[3][STG_E];

    const int tid  = threadIdx.x;
    const int wid  = tid >> 5;
    const int lane = tid & 31;
    const int wm   = wid & 1;
    const int wn   = wid >> 1;
    const int m0   = blockIdx.y * 128;
    const int n0   = blockIdx.x * 128;
    const int K    = EMB;
    const int NIT  = 192;

    const __nv_bfloat16* Bh = mode ? g_wo_hi : g_wq_hi;
    const __nv_bfloat16* Bl = mode ? g_wo_lo : g_wq_lo;
    float* C = mode ? Cext : (float*)g_qkv;

    float acc[4][4][4];
#pragma unroll
    for (int i = 0; i < 4; i++)
#pragma unroll
        for (int j = 0; j < 4; j++)
#pragma unroll
            for (int k = 0; k < 4; k++) acc[i][j][k] = 0.f;

    const int lr = tid >> 1;
    const int lc = (tid & 1) * 8;

    const int a_lrow  = lane & 15;
    const int a_lcol  = (lane >> 4) * 8;
    const int b_lrow  = (lane & 7) + ((lane >> 4) << 3);
    const int b_lcol  = ((lane >> 3) & 1) * 8;

    const uint32_t sA = smem_u32(As);
    const uint32_t sB = smem_u32(Bs);
    const uint32_t dstA = sA + ((uint32_t)(lr * STR3 + lc) << 1);
    const uint32_t dstB = sB + ((uint32_t)(lr * STR3 + lc) << 1);

    auto issue_tile = [&](int t) {
        const int seg = t >> 6;
        const int kk  = (t & 63) * 16;
        const __nv_bfloat16* Ap = (seg < 2)  ? g_a_hi : g_a_lo;
        const __nv_bfloat16* Bp = (seg == 1) ? Bl : Bh;
        const uint32_t so = (uint32_t)(t % 3) * (STG_E * 2);
        cp_async16(dstA + so, Ap + (size_t)(m0 + lr) * K + kk + lc);
        cp_async16(dstB + so, Bp + (size_t)(n0 + lr) * K + kk + lc);
    };

    issue_tile(0); cp_commit();
    issue_tile(1); cp_commit();

    for (int it = 0; it < NIT; it++) {
        cp_wait1();
        __syncthreads();

        const uint32_t so    = (uint32_t)(it % 3) * (STG_E * 2);
        const uint32_t baseA = sA + so;
        const uint32_t baseB = sB + so;

        uint32_t a[4][4], b[2][4];
#pragma unroll
        for (int mf = 0; mf < 4; mf++) {
            uint32_t addr = baseA +
                ((uint32_t)((wm * 64 + mf * 16 + a_lrow) * STR3 + a_lcol) << 1);
            ldmx4(a[mf], addr);
        }
#pragma unroll
        for (int nf2 = 0; nf2 < 2; nf2++) {
            uint32_t addr = baseB +
                ((uint32_t)((wn * 32 + nf2 * 16 + b_lrow) * STR3 + b_lcol) << 1);
            ldmx4(b[nf2], addr);
        }
#pragma unroll
        for (int mf = 0; mf < 4; mf++) {
#pragma unroll
            for (int nf = 0; nf < 4; nf++) {
                uint32_t b0 = b[nf >> 1][(nf & 1) * 2];
                uint32_t b1 = b[nf >> 1][(nf & 1) * 2 + 1];
                mma_bf16(acc[mf][nf], a[mf], b0, b1);
            }
        }

        if (it + 2 < NIT) issue_tile(it + 2);
        cp_commit();
    }

    // Epilogue
#pragma unroll
    for (int mf = 0; mf < 4; mf++) {
        const int r = m0 + wm * 64 + mf * 16 + (lane >> 2);
#pragma unroll
        for (int nf = 0; nf < 4; nf++) {
            const int c = n0 + wn * 32 + nf * 8 + (lane & 3) * 2;
            const float b0 = bias[c], b1 = bias[c + 1];
            float2 lo = make_float2(acc[mf][nf][0] + b0, acc[mf][nf][1] + b1);
            float2 hi = make_float2(acc[mf][nf][2] + b0, acc[mf][nf][3] + b1);
            *(float2*)&C[(size_t)r * N + c]       = lo;
            *(float2*)&C[(size_t)(r + 8) * N + c] = hi;
        }
    }
}

// ---------------------------------------------------------------------------
// Tensor-core flash attention, all fp16 (single-term QK and PV, fp32 accum).
// Block: (b,h) x 128-query tile; 8 warps x 16 query rows. Key-tiles of 64.
// ---------------------------------------------------------------------------
#define HPAD 72

__global__ __launch_bounds__(256) void attn_mma_kernel()
{
    __shared__ alignas(16) __half sK[64 * HPAD];
    __shared__ alignas(16) __half sV[64 * HPAD];

    const int tid  = threadIdx.x;
    const int w    = tid >> 5;
    const int lane = tid & 31;
    const int bh   = blockIdx.x;
    const int b    = bh >> 4;
    const int h    = bh & 15;
    const int q0   = blockIdx.y * 128;
    const int qoff = h * HD;
    const size_t grow0 = (size_t)(b * SEQ);

    const uint32_t aK = smem_u32(sK);
    const uint32_t aV = smem_u32(sV);

    const int a_lrow = lane & 15;
    const int a_lcol = (lane >> 4) * 8;
    const int b_lrow = (lane & 7) + ((lane >> 4) << 3);
    const int b_lcol = ((lane >> 3) & 1) * 8;
    const int v_lrow = lane & 15;
    const int v_lcol = (lane >> 4) * 8;

    // --- Load Q fragments via smem staging (uses sK as staging) ---
    uint32_t qf[4][4];
    {
        for (int u = 0; u < 4; u++) {
            int idx = tid + 256 * u;               // 0..1023
            int r = idx >> 3, c8 = (idx & 7) * 8;
            *(float4*)&sK[r * HPAD + c8] =
                *(const float4*)(g_qf + (grow0 + q0 + r) * EMB + qoff + c8);
        }
        __syncthreads();
#pragma unroll
        for (int d = 0; d < 4; d++) {
            uint32_t addr = aK +
                ((uint32_t)((w * 16 + a_lrow) * HPAD + d * 16 + a_lcol) << 1);
            ldmx4(qf[d], addr);
        }
        __syncthreads();
    }

    float o[8][4];
#pragma unroll
    for (int i = 0; i < 8; i++)
#pragma unroll
        for (int j = 0; j < 4; j++) o[i][j] = 0.f;
    float m_lo = -1e30f, m_hi = -1e30f, l_lo = 0.f, l_hi = 0.f;

    for (int kt = 0; kt < SEQ / 64; kt++) {
        // Load K and V tiles (64 x 64 fp16): 512 float4, 2 per thread each.
        {
            const size_t rbase = (grow0 + kt * 64) * EMB + qoff;
#pragma unroll
            for (int u = 0; u < 2; u++) {
                int idx = tid * 2 + u;
                int r = idx >> 3, c8 = (idx & 7) * 8;
                size_t g = rbase + (size_t)r * EMB + c8;
                *(float4*)&sK[r * HPAD + c8] = *(const float4*)(g_kf + g);
                *(float4*)&sV[r * HPAD + c8] = *(const float4*)(g_vf + g);
            }
        }
        __syncthreads();

        // S = Q @ K^T (fp16 single term)
        float s[8][4];
#pragma unroll
        for (int i = 0; i < 8; i++)
#pragma unroll
            for (int j = 0; j < 4; j++) s[i][j] = 0.f;

#pragma unroll
        for (int d = 0; d < 4; d++) {
#pragma unroll
            for (int nf2 = 0; nf2 < 4; nf2++) {
                uint32_t off = ((uint32_t)((nf2 * 16 + b_lrow) * HPAD
                                           + d * 16 + b_lcol) << 1);
                uint32_t bk[4];
                ldmx4(bk, aK + off);
                mma_f16(s[nf2 * 2],     qf[d], bk[0], bk[1]);
                mma_f16(s[nf2 * 2 + 1], qf[d], bk[2], bk[3]);
            }
        }

        // Online softmax (rows in lane quads; shfl 1,2 reductions)
        float rmax_lo = -1e30f, rmax_hi = -1e30f;
#pragma unroll
        for (int j = 0; j < 8; j++) {
            rmax_lo = fmaxf(rmax_lo, fmaxf(s[j][0], s[j][1]));
            rmax_hi = fmaxf(rmax_hi, fmaxf(s[j][2], s[j][3]));
        }
        rmax_lo = fmaxf(rmax_lo, __shfl_xor_sync(0xffffffffu, rmax_lo, 1));
        rmax_lo = fmaxf(rmax_lo, __shfl_xor_sync(0xffffffffu, rmax_lo, 2));
        rmax_hi = fmaxf(rmax_hi, __shfl_xor_sync(0xffffffffu, rmax_hi, 1));
        rmax_hi = fmaxf(rmax_hi, __shfl_xor_sync(0xffffffffu, rmax_hi, 2));

        float mn_lo = fmaxf(m_lo, rmax_lo);
        float mn_hi = fmaxf(m_hi, rmax_hi);
        float alpha_lo = __expf(m_lo - mn_lo);
        float alpha_hi = __expf(m_hi - mn_hi);

        uint32_t pl[8], ph[8];
        float rs_lo = 0.f, rs_hi = 0.f;
#pragma unroll
        for (int j = 0; j < 8; j++) {
            float p0 = __expf(s[j][0] - mn_lo);
            float p1 = __expf(s[j][1] - mn_lo);
            float p2 = __expf(s[j][2] - mn_hi);
            float p3 = __expf(s[j][3] - mn_hi);
            rs_lo += p0 + p1;
            rs_hi += p2 + p3;
            __half2 P01 = __floats2half2_rn(p0, p1);
            __half2 P23 = __floats2half2_rn(p2, p3);
            pl[j] = *(uint32_t*)&P01;
            ph[j] = *(uint32_t*)&P23;
        }
        rs_lo += __shfl_xor_sync(0xffffffffu, rs_lo, 1);
        rs_lo += __shfl_xor_sync(0xffffffffu, rs_lo, 2);
        rs_hi += __shfl_xor_sync(0xffffffffu, rs_hi, 1);
        rs_hi += __shfl_xor_sync(0xffffffffu, rs_hi, 2);

        l_lo = l_lo * alpha_lo + rs_lo;
        l_hi = l_hi * alpha_hi + rs_hi;
        m_lo = mn_lo;
        m_hi = mn_hi;
#pragma unroll
        for (int nf = 0; nf < 8; nf++) {
            o[nf][0] *= alpha_lo; o[nf][1] *= alpha_lo;
            o[nf][2] *= alpha_hi; o[nf][3] *= alpha_hi;
        }

        // O += P @ V (fp16 single term)
#pragma unroll
        for (int ks = 0; ks < 4; ks++) {
            uint32_t A[4] = {pl[ks * 2], ph[ks * 2], pl[ks * 2 + 1], ph[ks * 2 + 1]};
#pragma unroll
            for (int nc = 0; nc < 4; nc++) {
                uint32_t addr = aV +
                    ((uint32_t)((ks * 16 + v_lrow) * HPAD + nc * 16 + v_lcol) << 1);
                uint32_t bv[4];
                ldmx4t(bv, addr);
                mma_f16(o[nc * 2],     A, bv[0], bv[1]);
                mma_f16(o[nc * 2 + 1], A, bv[2], bv[3]);
            }
        }
        __syncthreads();
    }

    // Normalize and write ctx (fp32)
    const float inv_lo = 1.0f / l_lo;
    const float inv_hi = 1.0f / l_hi;
    const size_t row_lo = grow0 + q0 + w * 16 + (lane >> 2);
    const size_t row_hi = row_lo + 8;
#pragma unroll
    for (int nf = 0; nf < 8; nf++) {
        const int c = qoff + nf * 8 + (lane & 3) * 2;
        *(float2*)&g_ctx[row_lo * EMB + c] =
            make_float2(o[nf][0] * inv_lo, o[nf][1] * inv_lo);
        *(float2*)&g_ctx[row_hi * EMB + c] =
            make_float2(o[nf][2] * inv_hi, o[nf][3] * inv_hi);
    }
}

// ---------------------------------------------------------------------------
// Launch: pure kernel launches (graph-capture safe, no runtime API calls).
// ---------------------------------------------------------------------------
extern "C" void kernel_launch(void* const* d_in, const int* in_sizes, int n_in,
                              void* d_out, int out_size)
{
    const float* x     = (const float*)d_in[0];
    const float* W_qkv = (const float*)d_in[1];
    const float* b_qkv = (const float*)d_in[2];
    const float* W_o   = (const float*)d_in[3];
    const float* b_o   = (const float*)d_in[4];
    float* out = (float*)d_out;

    const size_t n4 = (size_t)MTOT * EMB / 4;

    // Preprocess: split x, transpose+split weights
    split_kernel<<<(unsigned)((n4 + 255) / 256), 256>>>(x, 0, n4);
    transpose_split_kernel<<<dim3(E3 / 32, EMB / 32), dim3(32, 8)>>>(W_qkv, 0, EMB, E3);
    transpose_split_kernel<<<dim3(EMB / 32, EMB / 32), dim3(32, 8)>>>(W_o, 1, EMB, EMB);

    // 1) QKV projection on tensor cores -> g_qkv
    tgemm_mma<<<dim3(E3 / 128, MTOT / 128), 256>>>(b_qkv, nullptr, E3, 0);

    // 2) Convert qkv -> fp16 operands, run tensor-core attention
    qkv_convert_kernel<<<(unsigned)((n4 + 255) / 256), 256>>>();
    attn_mma_kernel<<<dim3(BATCH * HEADS, SEQ / 128), 256>>>();

    // 3) Split ctx, output projection on tensor cores -> d_out
    split_kernel<<<(unsigned)((n4 + 255) / 256), 256>>>(nullptr, 1, n4);
    tgemm_mma<<<dim3(EMB / 128, MTOT / 128), 256>>>(b_o, out, EMB, 1);
}

// round 10
// speedup vs baseline: 3.6727x; 1.8578x over previous
#include <cuda_runtime.h>
#include <cuda_fp16.h>
#include <cstdint>

// Problem constants
#define EMB   1024
#define HEADS 16
#define HD    64
#define BATCH 4
#define SEQ   2048
#define MTOT  (BATCH * SEQ)          // 8192 rows
#define E3    (3 * EMB)              // 3072

// ---------------------------------------------------------------------------
// Scratch (static device globals — allocation-free per harness rules)
// ---------------------------------------------------------------------------
__device__ float g_qkv[(size_t)MTOT * E3];   // [B*S, 3E]  q|k|v (fp32)
__device__ float g_ctx[(size_t)MTOT * EMB];  // [B*S, E]   attention output
__device__ __half g_af [(size_t)MTOT * EMB];  // fp16 of x (pass 1) / ctx (pass 2)
__device__ __half g_wqf[(size_t)E3 * EMB];    // W_qkv^T fp16 [N,K]
__device__ __half g_wof[(size_t)EMB * EMB];   // W_o^T  fp16 [N,K]
// attention operands (fp16)
__device__ __half g_qf[(size_t)MTOT * EMB];  // Q * 0.125
__device__ __half g_kf[(size_t)MTOT * EMB];
__device__ __half g_vf[(size_t)MTOT * EMB];

// ---------------------------------------------------------------------------
// sm_80+ primitives (legal on plain sm_100 target)
// ---------------------------------------------------------------------------
__device__ __forceinline__ uint32_t smem_u32(const void* p) {
    uint32_t a;
    asm("{ .reg .u64 t; cvta.to.shared.u64 t, %1; cvt.u32.u64 %0, t; }"
        : "=r"(a) : "l"(p));
    return a;
}

__device__ __forceinline__ void ldmx4(uint32_t* r, uint32_t addr) {
    asm volatile("ldmatrix.sync.aligned.m8n8.x4.shared.b16 {%0,%1,%2,%3}, [%4];"
                 : "=r"(r[0]), "=r"(r[1]), "=r"(r[2]), "=r"(r[3]) : "r"(addr));
}

__device__ __forceinline__ void ldmx4t(uint32_t* r, uint32_t addr) {
    asm volatile("ldmatrix.sync.aligned.m8n8.x4.trans.shared.b16 {%0,%1,%2,%3}, [%4];"
                 : "=r"(r[0]), "=r"(r[1]), "=r"(r[2]), "=r"(r[3]) : "r"(addr));
}

__device__ __forceinline__ void mma_f16(float* d, const uint32_t* a,
                                        uint32_t b0, uint32_t b1) {
    asm volatile(
        "mma.sync.aligned.m16n8k16.row.col.f32.f16.f16.f32 "
        "{%0,%1,%2,%3}, {%4,%5,%6,%7}, {%8,%9}, {%0,%1,%2,%3};"
        : "+f"(d[0]), "+f"(d[1]), "+f"(d[2]), "+f"(d[3])
        : "r"(a[0]), "r"(a[1]), "r"(a[2]), "r"(a[3]), "r"(b0), "r"(b1));
}

__device__ __forceinline__ void cp_async16(uint32_t smem_dst, const void* gptr) {
    asm volatile("cp.async.cg.shared.global [%0], [%1], 16;"
                 :: "r"(smem_dst), "l"(gptr));
}
__device__ __forceinline__ void cp_commit() {
    asm volatile("cp.async.commit_group;");
}
__device__ __forceinline__ void cp_wait1() {
    asm volatile("cp.async.wait_group 1;");
}

// ---------------------------------------------------------------------------
// Preprocessing: fp32 -> fp16 convert. mode 0: X=xext, mode 1: X=g_ctx
// ---------------------------------------------------------------------------
__global__ __launch_bounds__(256) void cvt_kernel(const float* __restrict__ Xext,
                                                  int mode, size_t n4)
{
    size_t i = (size_t)blockIdx.x * blockDim.x + threadIdx.x;
    if (i >= n4) return;
    const float* X = (mode == 0) ? Xext : (const float*)g_ctx;
    float4 v = ((const float4*)X)[i];
    __half2 a = __floats2half2_rn(v.x, v.y);
    __half2 b = __floats2half2_rn(v.z, v.w);
    *(__half2*)(g_af + i * 4)     = a;
    *(__half2*)(g_af + i * 4 + 2) = b;
}

// ---------------------------------------------------------------------------
// Preprocessing: W [K,N] fp32 -> W^T fp16 [N,K]. mode 0: g_wqf, 1: g_wof
// ---------------------------------------------------------------------------
__global__ __launch_bounds__(256) void transpose_cvt_kernel(
    const float* __restrict__ W, int mode, int K, int N)
{
    __shared__ float t[32][33];
    const int n0 = blockIdx.x * 32, k0 = blockIdx.y * 32;
    const int tx = threadIdx.x, ty = threadIdx.y;
    for (int i = ty; i < 32; i += 8)
        t[i][tx] = W[(size_t)(k0 + i) * N + n0 + tx];
    __syncthreads();
    __half* T = mode ? g_wof : g_wqf;
    for (int i = ty; i < 32; i += 8) {
        float v = t[tx][i];                    // = W[k0+tx][n0+i]
        T[(size_t)(n0 + i) * K + k0 + tx] = __float2half_rn(v);
    }
}

// ---------------------------------------------------------------------------
// Convert g_qkv (fp32) -> fp16 attention operands (Q scaled by 0.125).
// ---------------------------------------------------------------------------
__global__ __launch_bounds__(256) void qkv_convert_kernel()
{
    size_t i = (size_t)blockIdx.x * blockDim.x + threadIdx.x;
    if (i >= (size_t)MTOT * EMB / 4) return;
    size_t row = i >> 8;
    size_t c4  = (i & 255) * 4;
    const float* base = g_qkv + row * E3;
    size_t o = row * EMB + c4;

    float4 q = *(const float4*)(base + c4);
    float4 k = *(const float4*)(base + EMB + c4);
    float4 v = *(const float4*)(base + 2 * EMB + c4);
    *(__half2*)(g_qf + o)     = __floats2half2_rn(q.x * 0.125f, q.y * 0.125f);
    *(__half2*)(g_qf + o + 2) = __floats2half2_rn(q.z * 0.125f, q.w * 0.125f);
    *(__half2*)(g_kf + o)     = __floats2half2_rn(k.x, k.y);
    *(__half2*)(g_kf + o + 2) = __floats2half2_rn(k.z, k.w);
    *(__half2*)(g_vf + o)     = __floats2half2_rn(v.x, v.y);
    *(__half2*)(g_vf + o + 2) = __floats2half2_rn(v.z, v.w);
}

// ---------------------------------------------------------------------------
// Tensor-core fp16 GEMM: C[M,N] = A[M,K]@B^T[N,K] + bias  (single term)
// Block 128x128, 8 warps (2m x 4n), warp 64x32, BK=16, stride 24,
// 3-stage cp.async pipeline. 64 k16-iters.
// mode 0: B=g_wqf, C=g_qkv (N=3072); mode 1: B=g_wof, C=Cext (N=1024)
// ---------------------------------------------------------------------------
#define STR3   24
#define STG_E  (128 * STR3)

__global__ __launch_bounds__(256, 2) void tgemm_mma(
    const float* __restrict__ bias, float* __restrict__ Cext, int N, int mode)
{
    __shared__ alignas(16) __half As[3][STG_E];
    __shared__ alignas(16) __half Bs[3][STG_E];

    const int tid  = threadIdx.x;
    const int wid  = tid >> 5;
    const int lane = tid & 31;
    const int wm   = wid & 1;
    const int wn   = wid >> 1;
    const int m0   = blockIdx.y * 128;
    const int n0   = blockIdx.x * 128;
    const int K    = EMB;
    const int NIT  = 64;                 // K/16

    const __half* Bsrc = mode ? g_wof : g_wqf;
    float* C = mode ? Cext : (float*)g_qkv;

    float acc[4][4][4];
#pragma unroll
    for (int i = 0; i < 4; i++)
#pragma unroll
        for (int j = 0; j < 4; j++)
#pragma unroll
            for (int k = 0; k < 4; k++) acc[i][j][k] = 0.f;

    const int lr = tid >> 1;
    const int lc = (tid & 1) * 8;

    const int a_lrow  = lane & 15;
    const int a_lcol  = (lane >> 4) * 8;
    const int b_lrow  = (lane & 7) + ((lane >> 4) << 3);
    const int b_lcol  = ((lane >> 3) & 1) * 8;

    const uint32_t sA = smem_u32(As);
    const uint32_t sB = smem_u32(Bs);
    const uint32_t dstA = sA + ((uint32_t)(lr * STR3 + lc) << 1);
    const uint32_t dstB = sB + ((uint32_t)(lr * STR3 + lc) << 1);

    auto issue_tile = [&](int t) {
        const int kk = t * 16;
        const uint32_t so = (uint32_t)(t % 3) * (STG_E * 2);
        cp_async16(dstA + so, g_af + (size_t)(m0 + lr) * K + kk + lc);
        cp_async16(dstB + so, Bsrc + (size_t)(n0 + lr) * K + kk + lc);
    };

    issue_tile(0); cp_commit();
    issue_tile(1); cp_commit();

    for (int it = 0; it < NIT; it++) {
        cp_wait1();
        __syncthreads();

        const uint32_t so    = (uint32_t)(it % 3) * (STG_E * 2);
        const uint32_t baseA = sA + so;
        const uint32_t baseB = sB + so;

        uint32_t a[4][4], b[2][4];
#pragma unroll
        for (int mf = 0; mf < 4; mf++) {
            uint32_t addr = baseA +
                ((uint32_t)((wm * 64 + mf * 16 + a_lrow) * STR3 + a_lcol) << 1);
            ldmx4(a[mf], addr);
        }
#pragma unroll
        for (int nf2 = 0; nf2 < 2; nf2++) {
            uint32_t addr = baseB +
                ((uint32_t)((wn * 32 + nf2 * 16 + b_lrow) * STR3 + b_lcol) << 1);
            ldmx4(b[nf2], addr);
        }
#pragma unroll
        for (int mf = 0; mf < 4; mf++) {
#pragma unroll
            for (int nf = 0; nf < 4; nf++) {
                uint32_t b0 = b[nf >> 1][(nf & 1) * 2];
                uint32_t b1 = b[nf >> 1][(nf & 1) * 2 + 1];
                mma_f16(acc[mf][nf], a[mf], b0, b1);
            }
        }

        if (it + 2 < NIT) issue_tile(it + 2);
        cp_commit();
    }

    // Epilogue
#pragma unroll
    for (int mf = 0; mf < 4; mf++) {
        const int r = m0 + wm * 64 + mf * 16 + (lane >> 2);
#pragma unroll
        for (int nf = 0; nf < 4; nf++) {
            const int c = n0 + wn * 32 + nf * 8 + (lane & 3) * 2;
            const float b0 = bias[c], b1 = bias[c + 1];
            float2 lo = make_float2(acc[mf][nf][0] + b0, acc[mf][nf][1] + b1);
            float2 hi = make_float2(acc[mf][nf][2] + b0, acc[mf][nf][3] + b1);
            *(float2*)&C[(size_t)r * N + c]       = lo;
            *(float2*)&C[(size_t)(r + 8) * N + c] = hi;
        }
    }
}

// ---------------------------------------------------------------------------
// Tensor-core flash attention, all fp16 (unchanged from round 9; 1.1e-4).
// Block: (b,h) x 128-query tile; 8 warps x 16 query rows. Key-tiles of 64.
// ---------------------------------------------------------------------------
#define HPAD 72

__global__ __launch_bounds__(256) void attn_mma_kernel()
{
    __shared__ alignas(16) __half sK[64 * HPAD];
    __shared__ alignas(16) __half sV[64 * HPAD];

    const int tid  = threadIdx.x;
    const int w    = tid >> 5;
    const int lane = tid & 31;
    const int bh   = blockIdx.x;
    const int b    = bh >> 4;
    const int h    = bh & 15;
    const int q0   = blockIdx.y * 128;
    const int qoff = h * HD;
    const size_t grow0 = (size_t)(b * SEQ);

    const uint32_t aK = smem_u32(sK);
    const uint32_t aV = smem_u32(sV);

    const int a_lrow = lane & 15;
    const int a_lcol = (lane >> 4) * 8;
    const int b_lrow = (lane & 7) + ((lane >> 4) << 3);
    const int b_lcol = ((lane >> 3) & 1) * 8;
    const int v_lrow = lane & 15;
    const int v_lcol = (lane >> 4) * 8;

    // --- Load Q fragments via smem staging (uses sK as staging) ---
    uint32_t qf[4][4];
    {
        for (int u = 0; u < 4; u++) {
            int idx = tid + 256 * u;               // 0..1023
            int r = idx >> 3, c8 = (idx & 7) * 8;
            *(float4*)&sK[r * HPAD + c8] =
                *(const float4*)(g_qf + (grow0 + q0 + r) * EMB + qoff + c8);
        }
        __syncthreads();
#pragma unroll
        for (int d = 0; d < 4; d++) {
            uint32_t addr = aK +
                ((uint32_t)((w * 16 + a_lrow) * HPAD + d * 16 + a_lcol) << 1);
            ldmx4(qf[d], addr);
        }
        __syncthreads();
    }

    float o[8][4];
#pragma unroll
    for (int i = 0; i < 8; i++)
#pragma unroll
        for (int j = 0; j < 4; j++) o[i][j] = 0.f;
    float m_lo = -1e30f, m_hi = -1e30f, l_lo = 0.f, l_hi = 0.f;

    for (int kt = 0; kt < SEQ / 64; kt++) {
        // Load K and V tiles (64 x 64 fp16)
        {
            const size_t rbase = (grow0 + kt * 64) * EMB + qoff;
#pragma unroll
            for (int u = 0; u < 2; u++) {
                int idx = tid * 2 + u;
                int r = idx >> 3, c8 = (idx & 7) * 8;
                size_t g = rbase + (size_t)r * EMB + c8;
                *(float4*)&sK[r * HPAD + c8] = *(const float4*)(g_kf + g);
                *(float4*)&sV[r * HPAD + c8] = *(const float4*)(g_vf + g);
            }
        }
        __syncthreads();

        // S = Q @ K^T
        float s[8][4];
#pragma unroll
        for (int i = 0; i < 8; i++)
#pragma unroll
            for (int j = 0; j < 4; j++) s[i][j] = 0.f;

#pragma unroll
        for (int d = 0; d < 4; d++) {
#pragma unroll
            for (int nf2 = 0; nf2 < 4; nf2++) {
                uint32_t off = ((uint32_t)((nf2 * 16 + b_lrow) * HPAD
                                           + d * 16 + b_lcol) << 1);
                uint32_t bk[4];
                ldmx4(bk, aK + off);
                mma_f16(s[nf2 * 2],     qf[d], bk[0], bk[1]);
                mma_f16(s[nf2 * 2 + 1], qf[d], bk[2], bk[3]);
            }
        }

        // Online softmax
        float rmax_lo = -1e30f, rmax_hi = -1e30f;
#pragma unroll
        for (int j = 0; j < 8; j++) {
            rmax_lo = fmaxf(rmax_lo, fmaxf(s[j][0], s[j][1]));
            rmax_hi = fmaxf(rmax_hi, fmaxf(s[j][2], s[j][3]));
        }
        rmax_lo = fmaxf(rmax_lo, __shfl_xor_sync(0xffffffffu, rmax_lo, 1));
        rmax_lo = fmaxf(rmax_lo, __shfl_xor_sync(0xffffffffu, rmax_lo, 2));
        rmax_hi = fmaxf(rmax_hi, __shfl_xor_sync(0xffffffffu, rmax_hi, 1));
        rmax_hi = fmaxf(rmax_hi, __shfl_xor_sync(0xffffffffu, rmax_hi, 2));

        float mn_lo = fmaxf(m_lo, rmax_lo);
        float mn_hi = fmaxf(m_hi, rmax_hi);
        float alpha_lo = __expf(m_lo - mn_lo);
        float alpha_hi = __expf(m_hi - mn_hi);

        uint32_t pl[8], ph[8];
        float rs_lo = 0.f, rs_hi = 0.f;
#pragma unroll
        for (int j = 0; j < 8; j++) {
            float p0 = __expf(s[j][0] - mn_lo);
            float p1 = __expf(s[j][1] - mn_lo);
            float p2 = __expf(s[j][2] - mn_hi);
            float p3 = __expf(s[j][3] - mn_hi);
            rs_lo += p0 + p1;
            rs_hi += p2 + p3;
            __half2 P01 = __floats2half2_rn(p0, p1);
            __half2 P23 = __floats2half2_rn(p2, p3);
            pl[j] = *(uint32_t*)&P01;
            ph[j] = *(uint32_t*)&P23;
        }
        rs_lo += __shfl_xor_sync(0xffffffffu, rs_lo, 1);
        rs_lo += __shfl_xor_sync(0xffffffffu, rs_lo, 2);
        rs_hi += __shfl_xor_sync(0xffffffffu, rs_hi, 1);
        rs_hi += __shfl_xor_sync(0xffffffffu, rs_hi, 2);

        l_lo = l_lo * alpha_lo + rs_lo;
        l_hi = l_hi * alpha_hi + rs_hi;
        m_lo = mn_lo;
        m_hi = mn_hi;
#pragma unroll
        for (int nf = 0; nf < 8; nf++) {
            o[nf][0] *= alpha_lo; o[nf][1] *= alpha_lo;
            o[nf][2] *= alpha_hi; o[nf][3] *= alpha_hi;
        }

        // O += P @ V
#pragma unroll
        for (int ks = 0; ks < 4; ks++) {
            uint32_t A[4] = {pl[ks * 2], ph[ks * 2], pl[ks * 2 + 1], ph[ks * 2 + 1]};
#pragma unroll
            for (int nc = 0; nc < 4; nc++) {
                uint32_t addr = aV +
                    ((uint32_t)((ks * 16 + v_lrow) * HPAD + nc * 16 + v_lcol) << 1);
                uint32_t bv[4];
                ldmx4t(bv, addr);
                mma_f16(o[nc * 2],     A, bv[0], bv[1]);
                mma_f16(o[nc * 2 + 1], A, bv[2], bv[3]);
            }
        }
        __syncthreads();
    }

    // Normalize and write ctx (fp32)
    const float inv_lo = 1.0f / l_lo;
    const float inv_hi = 1.0f / l_hi;
    const size_t row_lo = grow0 + q0 + w * 16 + (lane >> 2);
    const size_t row_hi = row_lo + 8;
#pragma unroll
    for (int nf = 0; nf < 8; nf++) {
        const int c = qoff + nf * 8 + (lane & 3) * 2;
        *(float2*)&g_ctx[row_lo * EMB + c] =
            make_float2(o[nf][0] * inv_lo, o[nf][1] * inv_lo);
        *(float2*)&g_ctx[row_hi * EMB + c] =
            make_float2(o[nf][2] * inv_hi, o[nf][3] * inv_hi);
    }
}

// ---------------------------------------------------------------------------
// Launch: pure kernel launches (graph-capture safe, no runtime API calls).
// ---------------------------------------------------------------------------
extern "C" void kernel_launch(void* const* d_in, const int* in_sizes, int n_in,
                              void* d_out, int out_size)
{
    const float* x     = (const float*)d_in[0];
    const float* W_qkv = (const float*)d_in[1];
    const float* b_qkv = (const float*)d_in[2];
    const float* W_o   = (const float*)d_in[3];
    const float* b_o   = (const float*)d_in[4];
    float* out = (float*)d_out;

    const size_t n4 = (size_t)MTOT * EMB / 4;

    // Preprocess: convert x, transpose+convert weights (fp16)
    cvt_kernel<<<(unsigned)((n4 + 255) / 256), 256>>>(x, 0, n4);
    transpose_cvt_kernel<<<dim3(E3 / 32, EMB / 32), dim3(32, 8)>>>(W_qkv, 0, EMB, E3);
    transpose_cvt_kernel<<<dim3(EMB / 32, EMB / 32), dim3(32, 8)>>>(W_o, 1, EMB, EMB);

    // 1) QKV projection (fp16 tensor cores) -> g_qkv
    tgemm_mma<<<dim3(E3 / 128, MTOT / 128), 256>>>(b_qkv, nullptr, E3, 0);

    // 2) Convert qkv -> fp16 operands, run tensor-core attention
    qkv_convert_kernel<<<(unsigned)((n4 + 255) / 256), 256>>>();
    attn_mma_kernel<<<dim3(BATCH * HEADS, SEQ / 128), 256>>>();

    // 3) Convert ctx -> fp16, output projection -> d_out
    cvt_kernel<<<(unsigned)((n4 + 255) / 256), 256>>>(nullptr, 1, n4);
    tgemm_mma<<<dim3(EMB / 128, MTOT / 128), 256>>>(b_o, out, EMB, 1);
}

// round 11
// speedup vs baseline: 4.0522x; 1.1033x over previous
#include <cuda_runtime.h>
#include <cuda_fp16.h>
#include <cstdint>

// Problem constants
#define EMB   1024
#define HEADS 16
#define HD    64
#define BATCH 4
#define SEQ   2048
#define MTOT  (BATCH * SEQ)          // 8192 rows
#define E3    (3 * EMB)              // 3072

// ---------------------------------------------------------------------------
// Scratch (static device globals — allocation-free per harness rules)
// ---------------------------------------------------------------------------
__device__ __half g_af [(size_t)MTOT * EMB];  // fp16 of x (pass 1) / attn out (pass 2)
__device__ __half g_wqf[(size_t)E3 * EMB];    // W_qkv^T fp16 [N,K]
__device__ __half g_wof[(size_t)EMB * EMB];   // W_o^T  fp16 [N,K]
__device__ __half g_qf[(size_t)MTOT * EMB];   // Q * 0.125 (fp16)
__device__ __half g_kf[(size_t)MTOT * EMB];
__device__ __half g_vf[(size_t)MTOT * EMB];

// ---------------------------------------------------------------------------
// sm_80+ primitives (legal on plain sm_100 target)
// ---------------------------------------------------------------------------
__device__ __forceinline__ uint32_t smem_u32(const void* p) {
    uint32_t a;
    asm("{ .reg .u64 t; cvta.to.shared.u64 t, %1; cvt.u32.u64 %0, t; }"
        : "=r"(a) : "l"(p));
    return a;
}

__device__ __forceinline__ void ldmx4(uint32_t* r, uint32_t addr) {
    asm volatile("ldmatrix.sync.aligned.m8n8.x4.shared.b16 {%0,%1,%2,%3}, [%4];"
                 : "=r"(r[0]), "=r"(r[1]), "=r"(r[2]), "=r"(r[3]) : "r"(addr));
}

__device__ __forceinline__ void ldmx4t(uint32_t* r, uint32_t addr) {
    asm volatile("ldmatrix.sync.aligned.m8n8.x4.trans.shared.b16 {%0,%1,%2,%3}, [%4];"
                 : "=r"(r[0]), "=r"(r[1]), "=r"(r[2]), "=r"(r[3]) : "r"(addr));
}

__device__ __forceinline__ void mma_f16(float* d, const uint32_t* a,
                                        uint32_t b0, uint32_t b1) {
    asm volatile(
        "mma.sync.aligned.m16n8k16.row.col.f32.f16.f16.f32 "
        "{%0,%1,%2,%3}, {%4,%5,%6,%7}, {%8,%9}, {%0,%1,%2,%3};"
        : "+f"(d[0]), "+f"(d[1]), "+f"(d[2]), "+f"(d[3])
        : "r"(a[0]), "r"(a[1]), "r"(a[2]), "r"(a[3]), "r"(b0), "r"(b1));
}

__device__ __forceinline__ void cp_async16(uint32_t smem_dst, const void* gptr) {
    asm volatile("cp.async.cg.shared.global [%0], [%1], 16;"
                 :: "r"(smem_dst), "l"(gptr));
}
__device__ __forceinline__ void cp_commit() {
    asm volatile("cp.async.commit_group;");
}
__device__ __forceinline__ void cp_wait0() {
    asm volatile("cp.async.wait_group 0;");
}
__device__ __forceinline__ void cp_wait1() {
    asm volatile("cp.async.wait_group 1;");
}

// ---------------------------------------------------------------------------
// Preprocessing: x fp32 -> fp16 (g_af)
// ---------------------------------------------------------------------------
__global__ __launch_bounds__(256) void cvt_kernel(const float* __restrict__ X,
                                                  size_t n4)
{
    size_t i = (size_t)blockIdx.x * blockDim.x + threadIdx.x;
    if (i >= n4) return;
    float4 v = ((const float4*)X)[i];
    *(__half2*)(g_af + i * 4)     = __floats2half2_rn(v.x, v.y);
    *(__half2*)(g_af + i * 4 + 2) = __floats2half2_rn(v.z, v.w);
}

// ---------------------------------------------------------------------------
// Preprocessing: W [K,N] fp32 -> W^T fp16 [N,K]. mode 0: g_wqf, 1: g_wof
// ---------------------------------------------------------------------------
__global__ __launch_bounds__(256) void transpose_cvt_kernel(
    const float* __restrict__ W, int mode, int K, int N)
{
    __shared__ float t[32][33];
    const int n0 = blockIdx.x * 32, k0 = blockIdx.y * 32;
    const int tx = threadIdx.x, ty = threadIdx.y;
    for (int i = ty; i < 32; i += 8)
        t[i][tx] = W[(size_t)(k0 + i) * N + n0 + tx];
    __syncthreads();
    __half* T = mode ? g_wof : g_wqf;
    for (int i = ty; i < 32; i += 8) {
        float v = t[tx][i];                    // = W[k0+tx][n0+i]
        T[(size_t)(n0 + i) * K + k0 + tx] = __float2half_rn(v);
    }
}

// ---------------------------------------------------------------------------
// Tensor-core fp16 GEMM: C = A[M,K]@B^T[N,K] + bias.
// Block 128x128, 8 warps (2m x 4n), warp 64x32, BK=16, stride 24,
// 3-stage cp.async pipeline. 64 k16-iters.
// mode 0: B=g_wqf, N=3072, epilogue -> fp16 g_qf(x0.125)/g_kf/g_vf
// mode 1: B=g_wof, N=1024, epilogue -> fp32 Cext (d_out)
// ---------------------------------------------------------------------------
#define STR3   24
#define STG_E  (128 * STR3)

__global__ __launch_bounds__(256, 2) void tgemm_mma(
    const float* __restrict__ bias, float* __restrict__ Cext, int N, int mode)
{
    __shared__ alignas(16) __half As[3][STG_E];
    __shared__ alignas(16) __half Bs[3][STG_E];

    const int tid  = threadIdx.x;
    const int wid  = tid >> 5;
    const int lane = tid & 31;
    const int wm   = wid & 1;
    const int wn   = wid >> 1;
    const int m0   = blockIdx.y * 128;
    const int n0   = blockIdx.x * 128;
    const int K    = EMB;
    const int NIT  = 64;                 // K/16

    const __half* Bsrc = mode ? g_wof : g_wqf;

    float acc[4][4][4];
#pragma unroll
    for (int i = 0; i < 4; i++)
#pragma unroll
        for (int j = 0; j < 4; j++)
#pragma unroll
            for (int k = 0; k < 4; k++) acc[i][j][k] = 0.f;

    const int lr = tid >> 1;
    const int lc = (tid & 1) * 8;

    const int a_lrow  = lane & 15;
    const int a_lcol  = (lane >> 4) * 8;
    const int b_lrow  = (lane & 7) + ((lane >> 4) << 3);
    const int b_lcol  = ((lane >> 3) & 1) * 8;

    const uint32_t sA = smem_u32(As);
    const uint32_t sB = smem_u32(Bs);
    const uint32_t dstA = sA + ((uint32_t)(lr * STR3 + lc) << 1);
    const uint32_t dstB = sB + ((uint32_t)(lr * STR3 + lc) << 1);

    auto issue_tile = [&](int t) {
        const int kk = t * 16;
        const uint32_t so = (uint32_t)(t % 3) * (STG_E * 2);
        cp_async16(dstA + so, g_af + (size_t)(m0 + lr) * K + kk + lc);
        cp_async16(dstB + so, Bsrc + (size_t)(n0 + lr) * K + kk + lc);
    };

    issue_tile(0); cp_commit();
    issue_tile(1); cp_commit();

    for (int it = 0; it < NIT; it++) {
        cp_wait1();
        __syncthreads();

        const uint32_t so    = (uint32_t)(it % 3) * (STG_E * 2);
        const uint32_t baseA = sA + so;
        const uint32_t baseB = sB + so;

        uint32_t a[4][4], b[2][4];
#pragma unroll
        for (int mf = 0; mf < 4; mf++) {
            uint32_t addr = baseA +
                ((uint32_t)((wm * 64 + mf * 16 + a_lrow) * STR3 + a_lcol) << 1);
            ldmx4(a[mf], addr);
        }
#pragma unroll
        for (int nf2 = 0; nf2 < 2; nf2++) {
            uint32_t addr = baseB +
                ((uint32_t)((wn * 32 + nf2 * 16 + b_lrow) * STR3 + b_lcol) << 1);
            ldmx4(b[nf2], addr);
        }
#pragma unroll
        for (int mf = 0; mf < 4; mf++) {
#pragma unroll
            for (int nf = 0; nf < 4; nf++) {
                uint32_t b0 = b[nf >> 1][(nf & 1) * 2];
                uint32_t b1 = b[nf >> 1][(nf & 1) * 2 + 1];
                mma_f16(acc[mf][nf], a[mf], b0, b1);
            }
        }

        if (it + 2 < NIT) issue_tile(it + 2);
        cp_commit();
    }

    // Epilogue
#pragma unroll
    for (int mf = 0; mf < 4; mf++) {
        const int r = m0 + wm * 64 + mf * 16 + (lane >> 2);
#pragma unroll
        for (int nf = 0; nf < 4; nf++) {
            const int c = n0 + wn * 32 + nf * 8 + (lane & 3) * 2;
            const float b0 = bias[c], b1 = bias[c + 1];
            float v0 = acc[mf][nf][0] + b0, v1 = acc[mf][nf][1] + b1;
            float v2 = acc[mf][nf][2] + b0, v3 = acc[mf][nf][3] + b1;
            if (mode == 0) {
                // fused convert: q (scaled) / k / v sections, fp16
                const int sec = c >> 10;           // 0..2 (1024-aligned)
                const int off = c & 1023;
                __half* dst = (sec == 0) ? g_qf : (sec == 1) ? g_kf : g_vf;
                const float sc = (sec == 0) ? 0.125f : 1.0f;
                *(__half2*)(dst + (size_t)r * EMB + off) =
                    __floats2half2_rn(v0 * sc, v1 * sc);
                *(__half2*)(dst + (size_t)(r + 8) * EMB + off) =
                    __floats2half2_rn(v2 * sc, v3 * sc);
            } else {
                *(float2*)&Cext[(size_t)r * N + c]       = make_float2(v0, v1);
                *(float2*)&Cext[(size_t)(r + 8) * N + c] = make_float2(v2, v3);
            }
        }
    }
}

// ---------------------------------------------------------------------------
// Tensor-core flash attention, all fp16, double-buffered cp.async K/V.
// Block: (b,h) x 128-query tile; 8 warps x 16 query rows. Key-tiles of 64.
// Output written as fp16 directly into g_af (input of the output projection).
// ---------------------------------------------------------------------------
#define HPAD 72
#define KVT  (64 * HPAD)                 // elements per K/V buffer

__global__ __launch_bounds__(256) void attn_mma_kernel()
{
    __shared__ alignas(16) __half sK[2][KVT];
    __shared__ alignas(16) __half sV[2][KVT];

    const int tid  = threadIdx.x;
    const int w    = tid >> 5;
    const int lane = tid & 31;
    const int bh   = blockIdx.x;
    const int b    = bh >> 4;
    const int h    = bh & 15;
    const int q0   = blockIdx.y * 128;
    const int qoff = h * HD;
    const size_t grow0 = (size_t)(b * SEQ);

    const uint32_t aK = smem_u32(sK);
    const uint32_t aV = smem_u32(sV);

    const int a_lrow = lane & 15;
    const int a_lcol = (lane >> 4) * 8;
    const int b_lrow = (lane & 7) + ((lane >> 4) << 3);
    const int b_lcol = ((lane >> 3) & 1) * 8;
    const int v_lrow = lane & 15;
    const int v_lcol = (lane >> 4) * 8;

    // Per-thread cp.async coords for one 64x64 tile: 2 float4 each for K and V
    const int kv_r0 = (tid * 2) >> 3,     kv_c0 = ((tid * 2) & 7) * 8;
    const int kv_r1 = (tid * 2 + 1) >> 3, kv_c1 = ((tid * 2 + 1) & 7) * 8;

    auto issue_kv = [&](int kt) {
        const size_t rbase = (grow0 + (size_t)kt * 64) * EMB + qoff;
        const uint32_t so = (uint32_t)(kt & 1) * (KVT * 2);
        cp_async16(aK + so + ((uint32_t)(kv_r0 * HPAD + kv_c0) << 1),
                   g_kf + rbase + (size_t)kv_r0 * EMB + kv_c0);
        cp_async16(aK + so + ((uint32_t)(kv_r1 * HPAD + kv_c1) << 1),
                   g_kf + rbase + (size_t)kv_r1 * EMB + kv_c1);
        cp_async16(aV + so + ((uint32_t)(kv_r0 * HPAD + kv_c0) << 1),
                   g_vf + rbase + (size_t)kv_r0 * EMB + kv_c0);
        cp_async16(aV + so + ((uint32_t)(kv_r1 * HPAD + kv_c1) << 1),
                   g_vf + rbase + (size_t)kv_r1 * EMB + kv_c1);
    };

    // --- Load Q fragments via smem staging (uses sK[0]+sK[1] as 128-row stage)
    uint32_t qf[4][4];
    {
        for (int u = 0; u < 4; u++) {
            int idx = tid + 256 * u;               // 0..1023
            int r = idx >> 3, c8 = (idx & 7) * 8;
            *(float4*)&sK[0][r * HPAD + c8] =
                *(const float4*)(g_qf + (grow0 + q0 + r) * EMB + qoff + c8);
        }
        __syncthreads();
#pragma unroll
        for (int d = 0; d < 4; d++) {
            uint32_t addr = aK +
                ((uint32_t)((w * 16 + a_lrow) * HPAD + d * 16 + a_lcol) << 1);
            ldmx4(qf[d], addr);
        }
        __syncthreads();       // Q frags extracted before cp.async overwrites
    }

    float o[8][4];
#pragma unroll
    for (int i = 0; i < 8; i++)
#pragma unroll
        for (int j = 0; j < 4; j++) o[i][j] = 0.f;
    float m_lo = -1e30f, m_hi = -1e30f, l_lo = 0.f, l_hi = 0.f;

    issue_kv(0); cp_commit();

    for (int kt = 0; kt < SEQ / 64; kt++) {
        cp_wait0();
        __syncthreads();       // tile kt resident; prior compute done

        if (kt + 1 < SEQ / 64) { issue_kv(kt + 1); cp_commit(); }

        const uint32_t so = (uint32_t)(kt & 1) * (KVT * 2);
        const uint32_t bK = aK + so;
        const uint32_t bV = aV + so;

        // S = Q @ K^T
        float s[8][4];
#pragma unroll
        for (int i = 0; i < 8; i++)
#pragma unroll
            for (int j = 0; j < 4; j++) s[i][j] = 0.f;

#pragma unroll
        for (int d = 0; d < 4; d++) {
#pragma unroll
            for (int nf2 = 0; nf2 < 4; nf2++) {
                uint32_t off = ((uint32_t)((nf2 * 16 + b_lrow) * HPAD
                                           + d * 16 + b_lcol) << 1);
                uint32_t bk[4];
                ldmx4(bk, bK + off);
                mma_f16(s[nf2 * 2],     qf[d], bk[0], bk[1]);
                mma_f16(s[nf2 * 2 + 1], qf[d], bk[2], bk[3]);
            }
        }

        // Online softmax
        float rmax_lo = -1e30f, rmax_hi = -1e30f;
#pragma unroll
        for (int j = 0; j < 8; j++) {
            rmax_lo = fmaxf(rmax_lo, fmaxf(s[j][0], s[j][1]));
            rmax_hi = fmaxf(rmax_hi, fmaxf(s[j][2], s[j][3]));
        }
        rmax_lo = fmaxf(rmax_lo, __shfl_xor_sync(0xffffffffu, rmax_lo, 1));
        rmax_lo = fmaxf(rmax_lo, __shfl_xor_sync(0xffffffffu, rmax_lo, 2));
        rmax_hi = fmaxf(rmax_hi, __shfl_xor_sync(0xffffffffu, rmax_hi, 1));
        rmax_hi = fmaxf(rmax_hi, __shfl_xor_sync(0xffffffffu, rmax_hi, 2));

        float mn_lo = fmaxf(m_lo, rmax_lo);
        float mn_hi = fmaxf(m_hi, rmax_hi);
        float alpha_lo = __expf(m_lo - mn_lo);
        float alpha_hi = __expf(m_hi - mn_hi);

        uint32_t pl[8], ph[8];
        float rs_lo = 0.f, rs_hi = 0.f;
#pragma unroll
        for (int j = 0; j < 8; j++) {
            float p0 = __expf(s[j][0] - mn_lo);
            float p1 = __expf(s[j][1] - mn_lo);
            float p2 = __expf(s[j][2] - mn_hi);
            float p3 = __expf(s[j][3] - mn_hi);
            rs_lo += p0 + p1;
            rs_hi += p2 + p3;
            __half2 P01 = __floats2half2_rn(p0, p1);
            __half2 P23 = __floats2half2_rn(p2, p3);
            pl[j] = *(uint32_t*)&P01;
            ph[j] = *(uint32_t*)&P23;
        }
        rs_lo += __shfl_xor_sync(0xffffffffu, rs_lo, 1);
        rs_lo += __shfl_xor_sync(0xffffffffu, rs_lo, 2);
        rs_hi += __shfl_xor_sync(0xffffffffu, rs_hi, 1);
        rs_hi += __shfl_xor_sync(0xffffffffu, rs_hi, 2);

        l_lo = l_lo * alpha_lo + rs_lo;
        l_hi = l_hi * alpha_hi + rs_hi;
        m_lo = mn_lo;
        m_hi = mn_hi;
#pragma unroll
        for (int nf = 0; nf < 8; nf++) {
            o[nf][0] *= alpha_lo; o[nf][1] *= alpha_lo;
            o[nf][2] *= alpha_hi; o[nf][3] *= alpha_hi;
        }

        // O += P @ V
#pragma unroll
        for (int ks = 0; ks < 4; ks++) {
            uint32_t A[4] = {pl[ks * 2], ph[ks * 2], pl[ks * 2 + 1], ph[ks * 2 + 1]};
#pragma unroll
            for (int nc = 0; nc < 4; nc++) {
                uint32_t addr = bV +
                    ((uint32_t)((ks * 16 + v_lrow) * HPAD + nc * 16 + v_lcol) << 1);
                uint32_t bv[4];
                ldmx4t(bv, addr);
                mma_f16(o[nc * 2],     A, bv[0], bv[1]);
                mma_f16(o[nc * 2 + 1], A, bv[2], bv[3]);
            }
        }
    }

    // Normalize and write fp16 output directly into g_af
    const float inv_lo = 1.0f / l_lo;
    const float inv_hi = 1.0f / l_hi;
    const size_t row_lo = grow0 + q0 + w * 16 + (lane >> 2);
    const size_t row_hi = row_lo + 8;
#pragma unroll
    for (int nf = 0; nf < 8; nf++) {
        const int c = qoff + nf * 8 + (lane & 3) * 2;
        *(__half2*)(g_af + row_lo * EMB + c) =
            __floats2half2_rn(o[nf][0] * inv_lo, o[nf][1] * inv_lo);
        *(__half2*)(g_af + row_hi * EMB + c) =
            __floats2half2_rn(o[nf][2] * inv_hi, o[nf][3] * inv_hi);
    }
}

// ---------------------------------------------------------------------------
// Launch: pure kernel launches (graph-capture safe, no runtime API calls).
// ---------------------------------------------------------------------------
extern "C" void kernel_launch(void* const* d_in, const int* in_sizes, int n_in,
                              void* d_out, int out_size)
{
    const float* x     = (const float*)d_in[0];
    const float* W_qkv = (const float*)d_in[1];
    const float* b_qkv = (const float*)d_in[2];
    const float* W_o   = (const float*)d_in[3];
    const float* b_o   = (const float*)d_in[4];
    float* out = (float*)d_out;

    const size_t n4 = (size_t)MTOT * EMB / 4;

    // Preprocess: convert x, transpose+convert weights (fp16)
    cvt_kernel<<<(unsigned)((n4 + 255) / 256), 256>>>(x, n4);
    transpose_cvt_kernel<<<dim3(E3 / 32, EMB / 32), dim3(32, 8)>>>(W_qkv, 0, EMB, E3);
    transpose_cvt_kernel<<<dim3(EMB / 32, EMB / 32), dim3(32, 8)>>>(W_o, 1, EMB, EMB);

    // 1) QKV projection -> fused fp16 q/k/v epilogue
    tgemm_mma<<<dim3(E3 / 128, MTOT / 128), 256>>>(b_qkv, nullptr, E3, 0);

    // 2) Flash attention -> fp16 output into g_af
    attn_mma_kernel<<<dim3(BATCH * HEADS, SEQ / 128), 256>>>();

    // 3) Output projection -> d_out (fp32)
    tgemm_mma<<<dim3(EMB / 128, MTOT / 128), 256>>>(b_o, out, EMB, 1);
}